// round 5
// baseline (speedup 1.0000x reference)
#include <cuda_runtime.h>
#include <cuda_bf16.h>
#include <math.h>
#include <stdint.h>

// Problem constants
#define Bn   2
#define Sn   2048
#define Dn   1024
#define Hn   16
#define DHn  64
#define Mn   (Bn*Sn)          // 4096 rows
#define DFF  (4*Dn)           // 4096
#define DG   (2*Dn)           // 2048
#define EPSV 1e-5f

// -------------------- scratch (device globals; no allocation) --------------------
__device__ float g_xn1 [Mn*Dn];
__device__ float g_q   [Mn*Dn];
__device__ float g_k   [Mn*Dn];
__device__ float g_v   [Mn*Dn];
__device__ float g_attn[Mn*Dn];
__device__ float g_x1  [Mn*Dn];
__device__ float g_xn2 [Mn*Dn];
__device__ float g_h   [Mn*DFF];
__device__ float g_glu [Mn*DG];
__device__ float g_wr  [10485760];   // rounded+TRANSPOSED weights

#define WOFF_Q  0
#define WOFF_K  1048576
#define WOFF_V  2097152
#define WOFF_O  3145728
#define WOFF_1  4194304
#define WOFF_2  8388608

// -------------------- helpers --------------------
__device__ __forceinline__ uint32_t f2tf(float f) {
    uint32_t r;
    asm("cvt.rna.tf32.f32 %0, %1;" : "=r"(r) : "f"(f));
    return r;
}
__device__ __forceinline__ float f2tff(float f) { return __uint_as_float(f2tf(f)); }

__device__ __forceinline__ void mma_tf32(float c[4], const uint32_t a[4],
                                         uint32_t b0, uint32_t b1) {
    asm volatile(
        "mma.sync.aligned.m16n8k8.row.col.f32.tf32.tf32.f32 "
        "{%0,%1,%2,%3}, {%4,%5,%6,%7}, {%8,%9}, {%0,%1,%2,%3};"
        : "+f"(c[0]), "+f"(c[1]), "+f"(c[2]), "+f"(c[3])
        : "r"(a[0]), "r"(a[1]), "r"(a[2]), "r"(a[3]), "r"(b0), "r"(b1));
}

__device__ __forceinline__ uint32_t smem_u32(const void* p) {
    uint32_t a;
    asm("{ .reg .u64 t; cvta.to.shared.u64 t, %1; cvt.u32.u64 %0, t; }"
        : "=r"(a) : "l"(p));
    return a;
}

__device__ __forceinline__ void ldsm4(uint32_t r[4], uint32_t addr) {
    asm volatile("ldmatrix.sync.aligned.m8n8.x4.shared.b16 {%0,%1,%2,%3}, [%4];"
        : "=r"(r[0]), "=r"(r[1]), "=r"(r[2]), "=r"(r[3]) : "r"(addr));
}

__device__ __forceinline__ void cp16(uint32_t dst, const void* src) {
    asm volatile("cp.async.cg.shared.global [%0], [%1], 16;" :: "r"(dst), "l"(src) : "memory");
}
__device__ __forceinline__ void cp_commit() { asm volatile("cp.async.commit_group;" ::: "memory"); }
template<int N>
__device__ __forceinline__ void cp_wait() { asm volatile("cp.async.wait_group %0;" :: "n"(N) : "memory"); }

// ==================== weight round (tf32) + transpose: dst[N][K] = rna(src[K][N]) ====================
__global__ __launch_bounds__(256) void roundw_t(const float* __restrict__ src,
                                                float* __restrict__ dst, int K, int N) {
    __shared__ float tile[32][33];
    const int bn = blockIdx.x * 32, bk = blockIdx.y * 32;
    const int tx = threadIdx.x & 31, ty = threadIdx.x >> 5;   // ty 0..7
    #pragma unroll
    for (int r = 0; r < 4; ++r)
        tile[ty + 8*r][tx] = f2tff(src[(size_t)(bk + ty + 8*r) * N + bn + tx]);
    __syncthreads();
    #pragma unroll
    for (int r = 0; r < 4; ++r)
        dst[(size_t)(bn + ty + 8*r) * K + bk + tx] = tile[tx][ty + 8*r];
}

// ==================== LayerNorm (tf32-rounded out) ====================
__global__ __launch_bounds__(256) void ln_kernel(const float* __restrict__ x,
                                                 const float* __restrict__ gamma,
                                                 const float* __restrict__ beta,
                                                 float* __restrict__ out) {
    const int row = blockIdx.x;
    const int tid = threadIdx.x;
    const float4* xr = (const float4*)(x + (size_t)row * Dn);
    float4 v = xr[tid];
    float s  = v.x + v.y + v.z + v.w;
    float ss = v.x*v.x + v.y*v.y + v.z*v.z + v.w*v.w;
    #pragma unroll
    for (int off = 16; off > 0; off >>= 1) {
        s  += __shfl_xor_sync(0xffffffffu, s,  off);
        ss += __shfl_xor_sync(0xffffffffu, ss, off);
    }
    __shared__ float red[2][8];
    const int wid = tid >> 5, lid = tid & 31;
    if (lid == 0) { red[0][wid] = s; red[1][wid] = ss; }
    __syncthreads();
    __shared__ float smu, srstd;
    if (tid == 0) {
        float ts = 0.f, tss = 0.f;
        #pragma unroll
        for (int i = 0; i < 8; ++i) { ts += red[0][i]; tss += red[1][i]; }
        float mu  = ts * (1.0f / Dn);
        float var = tss * (1.0f / Dn) - mu * mu;
        smu = mu; srstd = rsqrtf(var + EPSV);
    }
    __syncthreads();
    const float mu = smu, rstd = srstd;
    float4 g = ((const float4*)gamma)[tid];
    float4 b = ((const float4*)beta)[tid];
    float4 o;
    o.x = f2tff(g.x * (v.x - mu) * rstd + b.x);
    o.y = f2tff(g.y * (v.y - mu) * rstd + b.y);
    o.z = f2tff(g.z * (v.z - mu) * rstd + b.z);
    o.w = f2tff(g.w * (v.w - mu) * rstd + b.w);
    ((float4*)(out + (size_t)row * Dn))[tid] = o;
}

// ==================== TF32 GEMM, cp.async 4-stage + LDSM frags ====================
// C[M,N] = A[M,K] @ Bt[N,K]^T (+R). Both smem tiles 128 x 16, stride 20 floats.
#define BM 128
#define BN 128
#define BK 16
#define STAGES 4
#define TS 20
#define TILE_BYTES (128*TS*4)                 // 10240
#define GT_SMEM (STAGES*2*TILE_BYTES)         // 81920

template<bool RESID, bool ROUND>
__device__ __forceinline__ void gemm_body(
    const float* __restrict__ A, const float* __restrict__ Bt,
    const float* __restrict__ R, float* __restrict__ C,
    int M_, int N_, int K_)
{
    extern __shared__ char smem[];
    const uint32_t sbase = smem_u32(smem);

    const int tid = threadIdx.x;
    const int bx = blockIdx.x, by = blockIdx.y;
    const int wid = tid >> 5, lane = tid & 31;
    const int g = lane >> 2, t = lane & 3;
    const int wm = (wid >> 2) * 64, wn = (wid & 3) * 32;
    (void)g; (void)t;

    // cp.async: 512 16B chunks per tile, 2 per thread (rows tid>>2 and +64)
    const int ld_row = tid >> 2;
    const int ld_kc  = (tid & 3) * 4;

    // LDSM per-thread offsets
    const int a_row = ((lane >> 3) & 1) * 8 + (lane & 7);   // bit3 -> +8 rows
    const int a_kh  = ((lane >> 4) & 1) * 4;                // bit4 -> k+4
    const int b_row = ((lane >> 4) & 1) * 8 + (lane & 7);   // bit4 -> +8 rows
    const int b_kh  = ((lane >> 3) & 1) * 4;                // bit3 -> k+4

    const int nt = K_ >> 4;
    int kload = 0;

    auto issue = [&](int kt, int st) {
        const uint32_t da = sbase + st*(2*TILE_BYTES);
        const uint32_t db = da + TILE_BYTES;
        cp16(da + (ld_row     )*(TS*4) + ld_kc*4,
             &A[(size_t)(by*BM + ld_row     )*K_ + kt*BK + ld_kc]);
        cp16(da + (ld_row + 64)*(TS*4) + ld_kc*4,
             &A[(size_t)(by*BM + ld_row + 64)*K_ + kt*BK + ld_kc]);
        cp16(db + (ld_row     )*(TS*4) + ld_kc*4,
             &Bt[(size_t)(bx*BN + ld_row     )*K_ + kt*BK + ld_kc]);
        cp16(db + (ld_row + 64)*(TS*4) + ld_kc*4,
             &Bt[(size_t)(bx*BN + ld_row + 64)*K_ + kt*BK + ld_kc]);
    };

    float acc[4][4][4];
    #pragma unroll
    for (int i = 0; i < 4; ++i)
        #pragma unroll
        for (int j = 0; j < 4; ++j)
            #pragma unroll
            for (int e = 0; e < 4; ++e) acc[i][j][e] = 0.f;

    #pragma unroll
    for (int s = 0; s < STAGES-1; ++s) { issue(kload, s); cp_commit(); ++kload; }

    for (int kt = 0; kt < nt; ++kt) {
        cp_wait<STAGES-2>();
        __syncthreads();
        const uint32_t sa = sbase + (kt & (STAGES-1))*(2*TILE_BYTES);
        const uint32_t sb = sa + TILE_BYTES;
        #pragma unroll
        for (int kk = 0; kk < 2; ++kk) {
            const int k0 = kk * 8;
            uint32_t afr[4][4], bfr[4][2];
            #pragma unroll
            for (int i = 0; i < 4; ++i)
                ldsm4(afr[i], sa + ((wm + i*16 + a_row)*TS + k0 + a_kh)*4);
            #pragma unroll
            for (int jj = 0; jj < 2; ++jj) {
                uint32_t bq[4];
                ldsm4(bq, sb + ((wn + jj*16 + b_row)*TS + k0 + b_kh)*4);
                bfr[jj*2  ][0] = bq[0]; bfr[jj*2  ][1] = bq[1];
                bfr[jj*2+1][0] = bq[2]; bfr[jj*2+1][1] = bq[3];
            }
            #pragma unroll
            for (int i = 0; i < 4; ++i)
                #pragma unroll
                for (int j = 0; j < 4; ++j)
                    mma_tf32(acc[i][j], afr[i], bfr[j][0], bfr[j][1]);
        }
        if (kload < nt) { issue(kload, kload & (STAGES-1)); ++kload; }
        cp_commit();
    }

    // epilogue
    const int eg = lane >> 2, et = lane & 3;
    #pragma unroll
    for (int i = 0; i < 4; ++i) {
        const int row0 = by*BM + wm + i*16 + eg;
        const int row1 = row0 + 8;
        #pragma unroll
        for (int j = 0; j < 4; ++j) {
            const int col = bx*BN + wn + j*8 + et*2;
            float2 v0 = { acc[i][j][0], acc[i][j][1] };
            float2 v1 = { acc[i][j][2], acc[i][j][3] };
            if (RESID) {
                float2 r0 = *(const float2*)&R[(size_t)row0*N_ + col];
                float2 r1 = *(const float2*)&R[(size_t)row1*N_ + col];
                v0.x += r0.x; v0.y += r0.y;
                v1.x += r1.x; v1.y += r1.y;
            }
            if (ROUND) {
                v0.x = f2tff(v0.x); v0.y = f2tff(v0.y);
                v1.x = f2tff(v1.x); v1.y = f2tff(v1.y);
            }
            *(float2*)&C[(size_t)row0*N_ + col] = v0;
            *(float2*)&C[(size_t)row1*N_ + col] = v1;
        }
    }
}

template<bool RESID>
__global__ __launch_bounds__(256, 2) void gemm_k(
    const float* __restrict__ A, const float* __restrict__ Bt,
    const float* __restrict__ R, float* __restrict__ C,
    int M_, int N_, int K_)
{
    gemm_body<RESID, false>(A, Bt, R, C, M_, N_, K_);
}

__global__ __launch_bounds__(256, 2) void gemm_qkv(
    const float* __restrict__ A, const float* __restrict__ W,
    float* __restrict__ q, float* __restrict__ k, float* __restrict__ v)
{
    const int z = blockIdx.z;
    const float* Bt = W + (z == 0 ? WOFF_Q : z == 1 ? WOFF_K : WOFF_V);
    float* C = (z == 0) ? q : (z == 1) ? k : v;
    gemm_body<false, true>(A, Bt, nullptr, C, Mn, Dn, Dn);
}

// ==================== GLU (rounded) ====================
__global__ __launch_bounds__(256) void glu_kernel(const float* __restrict__ h,
                                                  float* __restrict__ g) {
    const int idx = blockIdx.x * blockDim.x + threadIdx.x;
    const int row = idx >> 9;
    const int c4  = idx & 511;
    float4 l = *(const float4*)&h[(size_t)row*DFF + c4*4];
    float4 r = *(const float4*)&h[(size_t)row*DFF + DG + c4*4];
    float4 o;
    o.x = f2tff(l.x / (1.f + expf(-r.x)));
    o.y = f2tff(l.y / (1.f + expf(-r.y)));
    o.z = f2tff(l.z / (1.f + expf(-r.z)));
    o.w = f2tff(l.w / (1.f + expf(-r.w)));
    *(float4*)&g[(size_t)row*DG + c4*4] = o;
}

// ==================== causal flash attention: 128 q-rows/block, 8 warps ====================
#define APAD 68
#define ATTN_SMEM ((64 + 64 + 128) * APAD * 4)   // Ks, Vs, Ps

__global__ __launch_bounds__(256) void attn_tf32(
    const float* __restrict__ Q, const float* __restrict__ K,
    const float* __restrict__ V, const int* __restrict__ mask,
    float* __restrict__ O) {
    extern __shared__ uint32_t sm_u[];
    uint32_t* Ks = sm_u;
    uint32_t* Vs = sm_u + 64*APAD;
    uint32_t* Ps = sm_u + 2*64*APAD;     // 128 rows
    __shared__ int msk[64];
    const uint32_t ks_u = smem_u32(Ks), vs_u = smem_u32(Vs);

    const int qt = blockIdx.x, h = blockIdx.y, b = blockIdx.z;
    const int tid = threadIdx.x;
    const int wid = tid >> 5, lane = tid & 31;
    const int g = lane >> 2, t = lane & 3;

    // Q fragments (already tf32-rounded by QKV epilogue)
    const float* Qb = Q + ((size_t)(b*Sn + qt*128 + wid*16))*Dn + h*DHn;
    uint32_t qa[8][4];
    #pragma unroll
    for (int ks = 0; ks < 8; ++ks) {
        qa[ks][0] = __float_as_uint(Qb[(size_t)(g    )*Dn + ks*8 + t    ]);
        qa[ks][1] = __float_as_uint(Qb[(size_t)(g + 8)*Dn + ks*8 + t    ]);
        qa[ks][2] = __float_as_uint(Qb[(size_t)(g    )*Dn + ks*8 + t + 4]);
        qa[ks][3] = __float_as_uint(Qb[(size_t)(g + 8)*Dn + ks*8 + t + 4]);
    }

    float o[8][4];
    #pragma unroll
    for (int j = 0; j < 8; ++j)
        #pragma unroll
        for (int e = 0; e < 4; ++e) o[j][e] = 0.f;
    float m0 = -1e30f, m1 = -1e30f, l0 = 0.f, l1 = 0.f;
    const float scale = 0.125f;

    const int rowg0 = qt*128 + wid*16 + g;
    const int rowg1 = rowg0 + 8;
    const int warp_top = qt*128 + wid*16 + 15;   // last q row this warp owns

    const int ktmax = 2*qt + 1;
    for (int kt = 0; kt <= ktmax; ++kt) {
        __syncthreads();
        {
            const float* Kb = K + (size_t)(b*Sn + kt*64)*Dn + h*DHn;
            const float* Vb = V + (size_t)(b*Sn + kt*64)*Dn + h*DHn;
            #pragma unroll
            for (int c = 0; c < 4; ++c) {
                const int idx = tid + c*256;
                const int rr = idx >> 4, q4 = idx & 15;
                cp16(ks_u + rr*(APAD*4) + q4*16, Kb + (size_t)rr*Dn + q4*4);
                cp16(vs_u + rr*(APAD*4) + q4*16, Vb + (size_t)rr*Dn + q4*4);
            }
            cp_commit();
        }
        if (tid < 64) msk[tid] = mask[b*Sn + kt*64 + tid];
        cp_wait<0>();
        __syncthreads();

        if (kt*64 > warp_top) continue;   // whole kv tile causally masked for this warp

        // S = Q @ K^T
        float sc[8][4];
        #pragma unroll
        for (int j = 0; j < 8; ++j)
            #pragma unroll
            for (int e = 0; e < 4; ++e) sc[j][e] = 0.f;
        #pragma unroll
        for (int ks = 0; ks < 8; ++ks) {
            #pragma unroll
            for (int j = 0; j < 8; ++j) {
                uint32_t b0 = Ks[(j*8 + g)*APAD + ks*8 + t    ];
                uint32_t b1 = Ks[(j*8 + g)*APAD + ks*8 + t + 4];
                mma_tf32(sc[j], qa[ks], b0, b1);
            }
        }

        #pragma unroll
        for (int j = 0; j < 8; ++j) {
            #pragma unroll
            for (int e = 0; e < 4; ++e) {
                const int cl  = j*8 + t*2 + (e & 1);
                const int kg  = kt*64 + cl;
                const int row = (e < 2) ? rowg0 : rowg1;
                const bool ok = (kg <= row) && (msk[cl] != 0);
                sc[j][e] = ok ? sc[j][e] * scale : -1e30f;
            }
        }

        float rm0 = -1e30f, rm1 = -1e30f;
        #pragma unroll
        for (int j = 0; j < 8; ++j) {
            rm0 = fmaxf(rm0, fmaxf(sc[j][0], sc[j][1]));
            rm1 = fmaxf(rm1, fmaxf(sc[j][2], sc[j][3]));
        }
        rm0 = fmaxf(rm0, __shfl_xor_sync(0xffffffffu, rm0, 1));
        rm0 = fmaxf(rm0, __shfl_xor_sync(0xffffffffu, rm0, 2));
        rm1 = fmaxf(rm1, __shfl_xor_sync(0xffffffffu, rm1, 1));
        rm1 = fmaxf(rm1, __shfl_xor_sync(0xffffffffu, rm1, 2));
        const float mn0 = fmaxf(m0, rm0), mn1 = fmaxf(m1, rm1);
        const float al0 = __expf(m0 - mn0), al1 = __expf(m1 - mn1);
        float s0 = 0.f, s1 = 0.f;
        #pragma unroll
        for (int j = 0; j < 8; ++j) {
            sc[j][0] = __expf(sc[j][0] - mn0);
            sc[j][1] = __expf(sc[j][1] - mn0);
            sc[j][2] = __expf(sc[j][2] - mn1);
            sc[j][3] = __expf(sc[j][3] - mn1);
            s0 += sc[j][0] + sc[j][1];
            s1 += sc[j][2] + sc[j][3];
        }
        s0 += __shfl_xor_sync(0xffffffffu, s0, 1);
        s0 += __shfl_xor_sync(0xffffffffu, s0, 2);
        s1 += __shfl_xor_sync(0xffffffffu, s1, 1);
        s1 += __shfl_xor_sync(0xffffffffu, s1, 2);
        l0 = l0 * al0 + s0;  m0 = mn0;
        l1 = l1 * al1 + s1;  m1 = mn1;
        #pragma unroll
        for (int j = 0; j < 8; ++j) {
            o[j][0] *= al0; o[j][1] *= al0;
            o[j][2] *= al1; o[j][3] *= al1;
        }

        #pragma unroll
        for (int j = 0; j < 8; ++j) {
            uint2 p0 = { f2tf(sc[j][0]), f2tf(sc[j][1]) };
            uint2 p1 = { f2tf(sc[j][2]), f2tf(sc[j][3]) };
            *(uint2*)&Ps[(wid*16 + g    )*APAD + j*8 + t*2] = p0;
            *(uint2*)&Ps[(wid*16 + g + 8)*APAD + j*8 + t*2] = p1;
        }
        __syncwarp();

        #pragma unroll
        for (int ks = 0; ks < 8; ++ks) {
            uint32_t pa[4];
            pa[0] = Ps[(wid*16 + g    )*APAD + ks*8 + t    ];
            pa[1] = Ps[(wid*16 + g + 8)*APAD + ks*8 + t    ];
            pa[2] = Ps[(wid*16 + g    )*APAD + ks*8 + t + 4];
            pa[3] = Ps[(wid*16 + g + 8)*APAD + ks*8 + t + 4];
            #pragma unroll
            for (int j = 0; j < 8; ++j) {
                uint32_t b0 = Vs[(ks*8 + t    )*APAD + j*8 + g];
                uint32_t b1 = Vs[(ks*8 + t + 4)*APAD + j*8 + g];
                mma_tf32(o[j], pa, b0, b1);
            }
        }
        __syncwarp();
    }

    const float i0 = 1.f / l0, i1 = 1.f / l1;
    float* Ob = O + ((size_t)(b*Sn + qt*128 + wid*16))*Dn + h*DHn;
    #pragma unroll
    for (int j = 0; j < 8; ++j) {
        float2 v0 = { f2tff(o[j][0] * i0), f2tff(o[j][1] * i0) };
        float2 v1 = { f2tff(o[j][2] * i1), f2tff(o[j][3] * i1) };
        *(float2*)&Ob[(size_t)(g    )*Dn + j*8 + t*2] = v0;
        *(float2*)&Ob[(size_t)(g + 8)*Dn + j*8 + t*2] = v1;
    }
}

// ==================== launch ====================
extern "C" void kernel_launch(void* const* d_in, const int* in_sizes, int n_in,
                              void* d_out, int out_size) {
    const float* x     = (const float*)d_in[0];
    const int*   amask = (const int*)  d_in[1];
    const float* Wq    = (const float*)d_in[2];
    const float* Wk    = (const float*)d_in[3];
    const float* Wv    = (const float*)d_in[4];
    const float* Wo    = (const float*)d_in[5];
    const float* W1    = (const float*)d_in[6];
    const float* W2    = (const float*)d_in[7];
    const float* gamma1= (const float*)d_in[8];
    const float* beta1 = (const float*)d_in[9];
    const float* gamma2= (const float*)d_in[10];
    const float* beta2 = (const float*)d_in[11];
    float* out = (float*)d_out;

    float *xn1, *q, *k, *v, *attn, *x1, *xn2, *hbuf, *glu, *wr;
    cudaGetSymbolAddress((void**)&xn1,  g_xn1);
    cudaGetSymbolAddress((void**)&q,    g_q);
    cudaGetSymbolAddress((void**)&k,    g_k);
    cudaGetSymbolAddress((void**)&v,    g_v);
    cudaGetSymbolAddress((void**)&attn, g_attn);
    cudaGetSymbolAddress((void**)&x1,   g_x1);
    cudaGetSymbolAddress((void**)&xn2,  g_xn2);
    cudaGetSymbolAddress((void**)&hbuf, g_h);
    cudaGetSymbolAddress((void**)&glu,  g_glu);
    cudaGetSymbolAddress((void**)&wr,   g_wr);

    cudaFuncSetAttribute(attn_tf32, cudaFuncAttributeMaxDynamicSharedMemorySize, ATTN_SMEM);
    cudaFuncSetAttribute(gemm_qkv,      cudaFuncAttributeMaxDynamicSharedMemorySize, GT_SMEM);
    cudaFuncSetAttribute(gemm_k<false>, cudaFuncAttributeMaxDynamicSharedMemorySize, GT_SMEM);
    cudaFuncSetAttribute(gemm_k<true>,  cudaFuncAttributeMaxDynamicSharedMemorySize, GT_SMEM);

    // 0. round + transpose weights
    roundw_t<<<dim3(Dn/32, Dn/32),  256>>>(Wq, wr + WOFF_Q, Dn, Dn);
    roundw_t<<<dim3(Dn/32, Dn/32),  256>>>(Wk, wr + WOFF_K, Dn, Dn);
    roundw_t<<<dim3(Dn/32, Dn/32),  256>>>(Wv, wr + WOFF_V, Dn, Dn);
    roundw_t<<<dim3(Dn/32, Dn/32),  256>>>(Wo, wr + WOFF_O, Dn, Dn);
    roundw_t<<<dim3(DFF/32, Dn/32), 256>>>(W1, wr + WOFF_1, Dn, DFF);
    roundw_t<<<dim3(Dn/32, DG/32),  256>>>(W2, wr + WOFF_2, DG, Dn);

    // 1. LN1
    ln_kernel<<<Mn, 256>>>(x, gamma1, beta1, xn1);

    // 2. fused Q,K,V projections
    dim3 gQKV(Dn/BN, Mn/BM, 3);
    gemm_qkv<<<gQKV, 256, GT_SMEM>>>(xn1, wr, q, k, v);

    // 3. causal attention (128 q rows per block)
    dim3 gA(Sn/128, Hn, Bn);
    attn_tf32<<<gA, 256, ATTN_SMEM>>>(q, k, v, amask, attn);

    // 4. output projection + residual
    dim3 gD(Dn/BN, Mn/BM);
    gemm_k<true><<<gD, 256, GT_SMEM>>>(attn, wr + WOFF_O, x, x1, Mn, Dn, Dn);

    // 5. LN2
    ln_kernel<<<Mn, 256>>>(x1, gamma2, beta2, xn2);

    // 6. W1 (N=4096)
    dim3 gF(DFF/BN, Mn/BM);
    gemm_k<false><<<gF, 256, GT_SMEM>>>(xn2, wr + WOFF_1, nullptr, hbuf, Mn, DFF, Dn);

    // 7. GLU
    glu_kernel<<<(Mn*DG/4)/256, 256>>>(hbuf, glu);

    // 8. W2 + residual -> out
    gemm_k<true><<<gD, 256, GT_SMEM>>>(glu, wr + WOFF_2, x1, out, Mn, Dn, DG);
}

// round 6
// speedup vs baseline: 1.7387x; 1.7387x over previous
#include <cuda_runtime.h>
#include <cuda_fp16.h>
#include <math.h>
#include <stdint.h>

// Problem constants
#define Bn   2
#define Sn   2048
#define Dn   1024
#define Hn   16
#define DHn  64
#define Mn   (Bn*Sn)          // 4096 rows
#define DFF  (4*Dn)           // 4096
#define DG   (2*Dn)           // 2048
#define EPSV 1e-5f

// -------------------- scratch (device globals; no allocation) --------------------
__device__ __half g_xn1 [Mn*Dn];
__device__ __half g_q   [Mn*Dn];
__device__ __half g_k   [Mn*Dn];
__device__ __half g_v   [Mn*Dn];
__device__ __half g_attn[Mn*Dn];
__device__ float  g_x1  [Mn*Dn];
__device__ __half g_xn2 [Mn*Dn];
__device__ float  g_h   [Mn*DFF];
__device__ __half g_glu [Mn*DG];
__device__ __half g_wh  [10485760];   // fp16 TRANSPOSED weights [N][K]

#define WOFF_Q  0
#define WOFF_K  1048576
#define WOFF_V  2097152
#define WOFF_O  3145728
#define WOFF_1  4194304
#define WOFF_2  8388608

// -------------------- helpers --------------------
__device__ __forceinline__ void mma_f16(float c[4], const uint32_t a[4],
                                        uint32_t b0, uint32_t b1) {
    asm volatile(
        "mma.sync.aligned.m16n8k16.row.col.f32.f16.f16.f32 "
        "{%0,%1,%2,%3}, {%4,%5,%6,%7}, {%8,%9}, {%0,%1,%2,%3};"
        : "+f"(c[0]), "+f"(c[1]), "+f"(c[2]), "+f"(c[3])
        : "r"(a[0]), "r"(a[1]), "r"(a[2]), "r"(a[3]), "r"(b0), "r"(b1));
}

__device__ __forceinline__ uint32_t smem_u32(const void* p) {
    uint32_t a;
    asm("{ .reg .u64 t; cvta.to.shared.u64 t, %1; cvt.u32.u64 %0, t; }"
        : "=r"(a) : "l"(p));
    return a;
}

__device__ __forceinline__ void ldsm4(uint32_t r[4], uint32_t addr) {
    asm volatile("ldmatrix.sync.aligned.m8n8.x4.shared.b16 {%0,%1,%2,%3}, [%4];"
        : "=r"(r[0]), "=r"(r[1]), "=r"(r[2]), "=r"(r[3]) : "r"(addr));
}
__device__ __forceinline__ void ldsm4t(uint32_t r[4], uint32_t addr) {
    asm volatile("ldmatrix.sync.aligned.m8n8.x4.trans.shared.b16 {%0,%1,%2,%3}, [%4];"
        : "=r"(r[0]), "=r"(r[1]), "=r"(r[2]), "=r"(r[3]) : "r"(addr));
}

__device__ __forceinline__ void cp16(uint32_t dst, const void* src) {
    asm volatile("cp.async.cg.shared.global [%0], [%1], 16;" :: "r"(dst), "l"(src) : "memory");
}
__device__ __forceinline__ void cp_commit() { asm volatile("cp.async.commit_group;" ::: "memory"); }
template<int N>
__device__ __forceinline__ void cp_wait() { asm volatile("cp.async.wait_group %0;" :: "n"(N) : "memory"); }

__device__ __forceinline__ uint32_t pack2(float x, float y) {
    __half2 h = __floats2half2_rn(x, y);
    return *(uint32_t*)&h;
}

// ==================== weight cvt fp16 + transpose: dst[N][K] = h(src[K][N]) ====================
__global__ __launch_bounds__(256) void cvtw_t(const float* __restrict__ src,
                                              __half* __restrict__ dst, int K, int N) {
    __shared__ float tile[32][33];
    const int bn = blockIdx.x * 32, bk = blockIdx.y * 32;
    const int tx = threadIdx.x & 31, ty = threadIdx.x >> 5;
    #pragma unroll
    for (int r = 0; r < 4; ++r)
        tile[ty + 8*r][tx] = src[(size_t)(bk + ty + 8*r) * N + bn + tx];
    __syncthreads();
    #pragma unroll
    for (int r = 0; r < 4; ++r)
        dst[(size_t)(bn + ty + 8*r) * K + bk + tx] = __float2half_rn(tile[tx][ty + 8*r]);
}

// ==================== LayerNorm (fp32 in -> fp16 out) ====================
__global__ __launch_bounds__(256) void ln_kernel(const float* __restrict__ x,
                                                 const float* __restrict__ gamma,
                                                 const float* __restrict__ beta,
                                                 __half* __restrict__ out) {
    const int row = blockIdx.x;
    const int tid = threadIdx.x;
    const float4* xr = (const float4*)(x + (size_t)row * Dn);
    float4 v = xr[tid];
    float s  = v.x + v.y + v.z + v.w;
    float ss = v.x*v.x + v.y*v.y + v.z*v.z + v.w*v.w;
    #pragma unroll
    for (int off = 16; off > 0; off >>= 1) {
        s  += __shfl_xor_sync(0xffffffffu, s,  off);
        ss += __shfl_xor_sync(0xffffffffu, ss, off);
    }
    __shared__ float red[2][8];
    const int wid = tid >> 5, lid = tid & 31;
    if (lid == 0) { red[0][wid] = s; red[1][wid] = ss; }
    __syncthreads();
    __shared__ float smu, srstd;
    if (tid == 0) {
        float ts = 0.f, tss = 0.f;
        #pragma unroll
        for (int i = 0; i < 8; ++i) { ts += red[0][i]; tss += red[1][i]; }
        float mu  = ts * (1.0f / Dn);
        float var = tss * (1.0f / Dn) - mu * mu;
        smu = mu; srstd = rsqrtf(var + EPSV);
    }
    __syncthreads();
    const float mu = smu, rstd = srstd;
    float4 g = ((const float4*)gamma)[tid];
    float4 b = ((const float4*)beta)[tid];
    uint2 u;
    u.x = pack2(g.x * (v.x - mu) * rstd + b.x, g.y * (v.y - mu) * rstd + b.y);
    u.y = pack2(g.z * (v.z - mu) * rstd + b.z, g.w * (v.w - mu) * rstd + b.w);
    ((uint2*)(out + (size_t)row * Dn))[tid] = u;
}

// ==================== FP16 tensor GEMM, cp.async 3-stage + ldmatrix ====================
// C[M,N] = A[M,K] @ Bt[N,K]^T (+R). smem tiles 128 rows x 32 halves, stride 56 halves (112B).
#define BM 128
#define BN 128
#define BKH 32                 // k halves per tile
#define STAGES 3
#define TSH 56                 // stride in halves (112B, 16B-multiple, ldsm conflict-free)
#define TILE_BYTES (128*TSH*2) // 14336
#define GT_SMEM (STAGES*2*TILE_BYTES)   // 86016

template<bool RESID, bool OUT_HALF>
__device__ __forceinline__ void gemm_body(
    const __half* __restrict__ A, const __half* __restrict__ Bt,
    const float* __restrict__ R, void* __restrict__ Cv,
    int M_, int N_, int K_)
{
    extern __shared__ char smem[];
    const uint32_t sbase = smem_u32(smem);

    const int tid = threadIdx.x;
    const int bx = blockIdx.x, by = blockIdx.y;
    const int wid = tid >> 5, lane = tid & 31;
    const int wm = (wid >> 2) * 64, wn = (wid & 3) * 32;

    // cp.async: 512 chunks/tile, 2 per thread
    const int ld_row = tid >> 2;
    const int ld_ch  = tid & 3;            // 16B chunk (8 halves)

    // ldmatrix thread address components
    const int lrow = lane & 15;
    const int lkh  = (lane >> 4) * 8;      // halves

    const int nt = K_ >> 5;
    int kload = 0;

    auto issue = [&](int kt, int st) {
        const uint32_t da = sbase + st*(2*TILE_BYTES);
        const uint32_t db = da + TILE_BYTES;
        cp16(da + (ld_row     )*(TSH*2) + ld_ch*16,
             &A[(size_t)(by*BM + ld_row     )*K_ + kt*BKH + ld_ch*8]);
        cp16(da + (ld_row + 64)*(TSH*2) + ld_ch*16,
             &A[(size_t)(by*BM + ld_row + 64)*K_ + kt*BKH + ld_ch*8]);
        cp16(db + (ld_row     )*(TSH*2) + ld_ch*16,
             &Bt[(size_t)(bx*BN + ld_row     )*K_ + kt*BKH + ld_ch*8]);
        cp16(db + (ld_row + 64)*(TSH*2) + ld_ch*16,
             &Bt[(size_t)(bx*BN + ld_row + 64)*K_ + kt*BKH + ld_ch*8]);
    };

    float acc[4][4][4];
    #pragma unroll
    for (int i = 0; i < 4; ++i)
        #pragma unroll
        for (int j = 0; j < 4; ++j)
            #pragma unroll
            for (int e = 0; e < 4; ++e) acc[i][j][e] = 0.f;

    issue(0, 0); cp_commit();
    issue(1, 1); cp_commit();
    kload = 2;

    int st = 0;
    for (int kt = 0; kt < nt; ++kt) {
        cp_wait<STAGES-2>();
        __syncthreads();
        const uint32_t sa = sbase + st*(2*TILE_BYTES);
        const uint32_t sb = sa + TILE_BYTES;
        #pragma unroll
        for (int kk = 0; kk < 2; ++kk) {        // two k16 steps
            uint32_t afr[4][4], bq[2][4];
            #pragma unroll
            for (int i = 0; i < 4; ++i)
                ldsm4(afr[i], sa + ((wm + i*16 + lrow)*TSH + kk*16 + lkh)*2);
            #pragma unroll
            for (int jj = 0; jj < 2; ++jj)
                ldsm4(bq[jj], sb + ((wn + jj*16 + lrow)*TSH + kk*16 + lkh)*2);
            #pragma unroll
            for (int i = 0; i < 4; ++i) {
                #pragma unroll
                for (int jj = 0; jj < 2; ++jj) {
                    mma_f16(acc[i][jj*2  ], afr[i], bq[jj][0], bq[jj][2]);
                    mma_f16(acc[i][jj*2+1], afr[i], bq[jj][1], bq[jj][3]);
                }
            }
        }
        if (kload < nt) {
            issue(kload, (st + 2 >= STAGES) ? st + 2 - STAGES : st + 2);
            ++kload;
        }
        cp_commit();
        if (++st == STAGES) st = 0;
    }

    // epilogue
    const int eg = lane >> 2, et = lane & 3;
    #pragma unroll
    for (int i = 0; i < 4; ++i) {
        const int row0 = by*BM + wm + i*16 + eg;
        const int row1 = row0 + 8;
        #pragma unroll
        for (int j = 0; j < 4; ++j) {
            const int col = bx*BN + wn + j*8 + et*2;
            if (OUT_HALF) {
                __half* C = (__half*)Cv;
                *(uint32_t*)&C[(size_t)row0*N_ + col] = pack2(acc[i][j][0], acc[i][j][1]);
                *(uint32_t*)&C[(size_t)row1*N_ + col] = pack2(acc[i][j][2], acc[i][j][3]);
            } else {
                float* C = (float*)Cv;
                float2 v0 = { acc[i][j][0], acc[i][j][1] };
                float2 v1 = { acc[i][j][2], acc[i][j][3] };
                if (RESID) {
                    float2 r0 = *(const float2*)&R[(size_t)row0*N_ + col];
                    float2 r1 = *(const float2*)&R[(size_t)row1*N_ + col];
                    v0.x += r0.x; v0.y += r0.y;
                    v1.x += r1.x; v1.y += r1.y;
                }
                *(float2*)&C[(size_t)row0*N_ + col] = v0;
                *(float2*)&C[(size_t)row1*N_ + col] = v1;
            }
        }
    }
}

template<bool RESID, bool OUT_HALF>
__global__ __launch_bounds__(256, 2) void gemm_k(
    const __half* __restrict__ A, const __half* __restrict__ Bt,
    const float* __restrict__ R, void* __restrict__ Cv,
    int M_, int N_, int K_)
{
    gemm_body<RESID, OUT_HALF>(A, Bt, R, Cv, M_, N_, K_);
}

__global__ __launch_bounds__(256, 2) void gemm_qkv(
    const __half* __restrict__ A, const __half* __restrict__ W,
    __half* __restrict__ q, __half* __restrict__ k, __half* __restrict__ v)
{
    const int z = blockIdx.z;
    const __half* Bt = W + (z == 0 ? WOFF_Q : z == 1 ? WOFF_K : WOFF_V);
    __half* C = (z == 0) ? q : (z == 1) ? k : v;
    gemm_body<false, true>(A, Bt, nullptr, C, Mn, Dn, Dn);
}

// ==================== GLU (fp32 h -> fp16 glu) ====================
__global__ __launch_bounds__(256) void glu_kernel(const float* __restrict__ h,
                                                  __half* __restrict__ g) {
    const int idx = blockIdx.x * blockDim.x + threadIdx.x;
    const int row = idx >> 9;
    const int c4  = idx & 511;
    float4 l = *(const float4*)&h[(size_t)row*DFF + c4*4];
    float4 r = *(const float4*)&h[(size_t)row*DFF + DG + c4*4];
    uint2 u;
    u.x = pack2(l.x / (1.f + expf(-r.x)), l.y / (1.f + expf(-r.y)));
    u.y = pack2(l.z / (1.f + expf(-r.z)), l.w / (1.f + expf(-r.w)));
    *(uint2*)&g[(size_t)row*DG + c4*4] = u;
}

// ==================== causal flash attention (fp16 MMA, no P smem) ====================
// grid (S/64, H, B), 128 threads (4 warps x 16 q rows)
#define KVS 72                 // smem stride halves (144B; 16B multiple; bank 4r distinct)
#define ATTN_SMEM (2*64*KVS*2) // 18432

__global__ __launch_bounds__(128) void attn_f16(
    const __half* __restrict__ Q, const __half* __restrict__ K,
    const __half* __restrict__ V, const int* __restrict__ mask,
    __half* __restrict__ O) {
    extern __shared__ __half smh[];
    __half* Ks = smh;
    __half* Vs = smh + 64*KVS;
    __shared__ int msk[64];
    const uint32_t ks_u = smem_u32(Ks), vs_u = smem_u32(Vs);

    const int qt = blockIdx.x, h = blockIdx.y, b = blockIdx.z;
    const int tid = threadIdx.x;
    const int wid = tid >> 5, lane = tid & 31;
    const int g = lane >> 2, t = lane & 3;
    const int lrow = lane & 15;
    const int lkh  = (lane >> 4) * 8;

    // Q fragments in registers: 4 ksteps of k16 over DH=64
    const __half* Qb = Q + ((size_t)(b*Sn + qt*64 + wid*16))*Dn + h*DHn;
    uint32_t qa[4][4];
    #pragma unroll
    for (int ks = 0; ks < 4; ++ks) {
        qa[ks][0] = *(const uint32_t*)&Qb[(size_t)(g    )*Dn + ks*16 + 2*t];
        qa[ks][1] = *(const uint32_t*)&Qb[(size_t)(g + 8)*Dn + ks*16 + 2*t];
        qa[ks][2] = *(const uint32_t*)&Qb[(size_t)(g    )*Dn + ks*16 + 8 + 2*t];
        qa[ks][3] = *(const uint32_t*)&Qb[(size_t)(g + 8)*Dn + ks*16 + 8 + 2*t];
    }

    float o[8][4];
    #pragma unroll
    for (int j = 0; j < 8; ++j)
        #pragma unroll
        for (int e = 0; e < 4; ++e) o[j][e] = 0.f;
    float m0 = -1e30f, m1 = -1e30f, l0 = 0.f, l1 = 0.f;
    const float scale = 0.125f;

    const int rowg0 = qt*64 + wid*16 + g;
    const int rowg1 = rowg0 + 8;

    for (int kt = 0; kt <= qt; ++kt) {
        __syncthreads();
        {
            const __half* Kb = K + (size_t)(b*Sn + kt*64)*Dn + h*DHn;
            const __half* Vb = V + (size_t)(b*Sn + kt*64)*Dn + h*DHn;
            #pragma unroll
            for (int c = 0; c < 4; ++c) {
                const int idx = tid + c*128;
                const int rr = idx >> 3, ch = idx & 7;
                cp16(ks_u + rr*(KVS*2) + ch*16, Kb + (size_t)rr*Dn + ch*8);
                cp16(vs_u + rr*(KVS*2) + ch*16, Vb + (size_t)rr*Dn + ch*8);
            }
            cp_commit();
        }
        if (tid < 64) msk[tid] = mask[b*Sn + kt*64 + tid];
        cp_wait<0>();
        __syncthreads();

        // S = Q @ K^T : per warp 16 x 64
        float sc[8][4];
        #pragma unroll
        for (int j = 0; j < 8; ++j)
            #pragma unroll
            for (int e = 0; e < 4; ++e) sc[j][e] = 0.f;
        #pragma unroll
        for (int ks = 0; ks < 4; ++ks) {
            #pragma unroll
            for (int jj = 0; jj < 4; ++jj) {      // seq n16 tiles
                uint32_t bq[4];
                ldsm4(bq, ks_u + ((jj*16 + lrow)*KVS + ks*16 + lkh)*2);
                mma_f16(sc[jj*2  ], qa[ks], bq[0], bq[2]);
                mma_f16(sc[jj*2+1], qa[ks], bq[1], bq[3]);
            }
        }

        // scale + causal + key mask
        #pragma unroll
        for (int j = 0; j < 8; ++j) {
            #pragma unroll
            for (int e = 0; e < 4; ++e) {
                const int cl  = j*8 + t*2 + (e & 1);
                const int kg  = kt*64 + cl;
                const int row = (e < 2) ? rowg0 : rowg1;
                const bool ok = (kg <= row) && (msk[cl] != 0);
                sc[j][e] = ok ? sc[j][e] * scale : -1e30f;
            }
        }

        // online softmax
        float rm0 = -1e30f, rm1 = -1e30f;
        #pragma unroll
        for (int j = 0; j < 8; ++j) {
            rm0 = fmaxf(rm0, fmaxf(sc[j][0], sc[j][1]));
            rm1 = fmaxf(rm1, fmaxf(sc[j][2], sc[j][3]));
        }
        rm0 = fmaxf(rm0, __shfl_xor_sync(0xffffffffu, rm0, 1));
        rm0 = fmaxf(rm0, __shfl_xor_sync(0xffffffffu, rm0, 2));
        rm1 = fmaxf(rm1, __shfl_xor_sync(0xffffffffu, rm1, 1));
        rm1 = fmaxf(rm1, __shfl_xor_sync(0xffffffffu, rm1, 2));
        const float mn0 = fmaxf(m0, rm0), mn1 = fmaxf(m1, rm1);
        const float al0 = __expf(m0 - mn0), al1 = __expf(m1 - mn1);
        float s0 = 0.f, s1 = 0.f;
        #pragma unroll
        for (int j = 0; j < 8; ++j) {
            sc[j][0] = __expf(sc[j][0] - mn0);
            sc[j][1] = __expf(sc[j][1] - mn0);
            sc[j][2] = __expf(sc[j][2] - mn1);
            sc[j][3] = __expf(sc[j][3] - mn1);
            s0 += sc[j][0] + sc[j][1];
            s1 += sc[j][2] + sc[j][3];
        }
        s0 += __shfl_xor_sync(0xffffffffu, s0, 1);
        s0 += __shfl_xor_sync(0xffffffffu, s0, 2);
        s1 += __shfl_xor_sync(0xffffffffu, s1, 1);
        s1 += __shfl_xor_sync(0xffffffffu, s1, 2);
        l0 = l0 * al0 + s0;  m0 = mn0;
        l1 = l1 * al1 + s1;  m1 = mn1;
        #pragma unroll
        for (int j = 0; j < 8; ++j) {
            o[j][0] *= al0; o[j][1] *= al0;
            o[j][2] *= al1; o[j][3] *= al1;
        }

        // O += P @ V : P fragments are direct repacks of sc (C->A layout match)
        #pragma unroll
        for (int ks = 0; ks < 4; ++ks) {          // seq k16 steps
            uint32_t pa[4];
            pa[0] = pack2(sc[2*ks  ][0], sc[2*ks  ][1]);
            pa[1] = pack2(sc[2*ks  ][2], sc[2*ks  ][3]);
            pa[2] = pack2(sc[2*ks+1][0], sc[2*ks+1][1]);
            pa[3] = pack2(sc[2*ks+1][2], sc[2*ks+1][3]);
            #pragma unroll
            for (int jj = 0; jj < 4; ++jj) {      // dh n16 tiles
                uint32_t bq[4];
                ldsm4t(bq, vs_u + ((ks*16 + lrow)*KVS + jj*16 + lkh)*2);
                mma_f16(o[jj*2  ], pa, bq[0], bq[1]);
                mma_f16(o[jj*2+1], pa, bq[2], bq[3]);
            }
        }
    }

    const float i0 = 1.f / l0, i1 = 1.f / l1;
    __half* Ob = O + ((size_t)(b*Sn + qt*64 + wid*16))*Dn + h*DHn;
    #pragma unroll
    for (int j = 0; j < 8; ++j) {
        *(uint32_t*)&Ob[(size_t)(g    )*Dn + j*8 + t*2] = pack2(o[j][0]*i0, o[j][1]*i0);
        *(uint32_t*)&Ob[(size_t)(g + 8)*Dn + j*8 + t*2] = pack2(o[j][2]*i1, o[j][3]*i1);
    }
}

// ==================== launch ====================
extern "C" void kernel_launch(void* const* d_in, const int* in_sizes, int n_in,
                              void* d_out, int out_size) {
    const float* x     = (const float*)d_in[0];
    const int*   amask = (const int*)  d_in[1];
    const float* Wq    = (const float*)d_in[2];
    const float* Wk    = (const float*)d_in[3];
    const float* Wv    = (const float*)d_in[4];
    const float* Wo    = (const float*)d_in[5];
    const float* W1    = (const float*)d_in[6];
    const float* W2    = (const float*)d_in[7];
    const float* gamma1= (const float*)d_in[8];
    const float* beta1 = (const float*)d_in[9];
    const float* gamma2= (const float*)d_in[10];
    const float* beta2 = (const float*)d_in[11];
    float* out = (float*)d_out;

    __half *xn1, *q, *k, *v, *attn, *xn2, *glu, *wh;
    float *x1, *hbuf;
    cudaGetSymbolAddress((void**)&xn1,  g_xn1);
    cudaGetSymbolAddress((void**)&q,    g_q);
    cudaGetSymbolAddress((void**)&k,    g_k);
    cudaGetSymbolAddress((void**)&v,    g_v);
    cudaGetSymbolAddress((void**)&attn, g_attn);
    cudaGetSymbolAddress((void**)&x1,   g_x1);
    cudaGetSymbolAddress((void**)&xn2,  g_xn2);
    cudaGetSymbolAddress((void**)&hbuf, g_h);
    cudaGetSymbolAddress((void**)&glu,  g_glu);
    cudaGetSymbolAddress((void**)&wh,   g_wh);

    cudaFuncSetAttribute(attn_f16, cudaFuncAttributeMaxDynamicSharedMemorySize, ATTN_SMEM);
    cudaFuncSetAttribute(gemm_qkv, cudaFuncAttributeMaxDynamicSharedMemorySize, GT_SMEM);
    cudaFuncSetAttribute((const void*)gemm_k<false,false>, cudaFuncAttributeMaxDynamicSharedMemorySize, GT_SMEM);
    cudaFuncSetAttribute((const void*)gemm_k<true,false>,  cudaFuncAttributeMaxDynamicSharedMemorySize, GT_SMEM);

    // 0. convert + transpose weights to fp16
    cvtw_t<<<dim3(Dn/32, Dn/32),  256>>>(Wq, wh + WOFF_Q, Dn, Dn);
    cvtw_t<<<dim3(Dn/32, Dn/32),  256>>>(Wk, wh + WOFF_K, Dn, Dn);
    cvtw_t<<<dim3(Dn/32, Dn/32),  256>>>(Wv, wh + WOFF_V, Dn, Dn);
    cvtw_t<<<dim3(Dn/32, Dn/32),  256>>>(Wo, wh + WOFF_O, Dn, Dn);
    cvtw_t<<<dim3(DFF/32, Dn/32), 256>>>(W1, wh + WOFF_1, Dn, DFF);
    cvtw_t<<<dim3(Dn/32, DG/32),  256>>>(W2, wh + WOFF_2, DG, Dn);

    // 1. LN1 -> fp16
    ln_kernel<<<Mn, 256>>>(x, gamma1, beta1, xn1);

    // 2. fused Q,K,V projections -> fp16
    dim3 gQKV(Dn/BN, Mn/BM, 3);
    gemm_qkv<<<gQKV, 256, GT_SMEM>>>(xn1, wh, q, k, v);

    // 3. causal attention -> fp16
    dim3 gA(Sn/64, Hn, Bn);
    attn_f16<<<gA, 128, ATTN_SMEM>>>(q, k, v, amask, attn);

    // 4. output projection + residual -> fp32 x1
    dim3 gD(Dn/BN, Mn/BM);
    gemm_k<true,false><<<gD, 256, GT_SMEM>>>(attn, wh + WOFF_O, x, x1, Mn, Dn, Dn);

    // 5. LN2 -> fp16
    ln_kernel<<<Mn, 256>>>(x1, gamma2, beta2, xn2);

    // 6. W1 (N=4096) -> fp32 h
    dim3 gF(DFF/BN, Mn/BM);
    gemm_k<false,false><<<gF, 256, GT_SMEM>>>(xn2, wh + WOFF_1, nullptr, hbuf, Mn, DFF, Dn);

    // 7. GLU -> fp16
    glu_kernel<<<(Mn*DG/4)/256, 256>>>(hbuf, glu);

    // 8. W2 + residual -> fp32 out
    gemm_k<true,false><<<gD, 256, GT_SMEM>>>(glu, wh + WOFF_2, x1, out, Mn, Dn, DG);
}

// round 7
// speedup vs baseline: 1.7680x; 1.0168x over previous
#include <cuda_runtime.h>
#include <cuda_fp16.h>
#include <math.h>
#include <stdint.h>

// Problem constants
#define Bn   2
#define Sn   2048
#define Dn   1024
#define Hn   16
#define DHn  64
#define Mn   (Bn*Sn)          // 4096 rows
#define DFF  (4*Dn)           // 4096
#define DG   (2*Dn)           // 2048
#define EPSV 1e-5f

// -------------------- scratch (device globals; no allocation) --------------------
__device__ __half g_xn1 [Mn*Dn];
__device__ __half g_q   [Mn*Dn];
__device__ __half g_k   [Mn*Dn];
__device__ __half g_v   [Mn*Dn];
__device__ __half g_attn[Mn*Dn];
__device__ float  g_x1  [Mn*Dn];
__device__ __half g_xn2 [Mn*Dn];
__device__ __half g_h   [Mn*DFF];    // fp16 now
__device__ __half g_glu [Mn*DG];
__device__ __half g_wh  [10485760];  // fp16 TRANSPOSED weights [N][K]

#define WOFF_Q  0
#define WOFF_K  1048576
#define WOFF_V  2097152
#define WOFF_O  3145728
#define WOFF_1  4194304
#define WOFF_2  8388608

// -------------------- helpers --------------------
__device__ __forceinline__ void mma_f16(float c[4], const uint32_t a[4],
                                        uint32_t b0, uint32_t b1) {
    asm volatile(
        "mma.sync.aligned.m16n8k16.row.col.f32.f16.f16.f32 "
        "{%0,%1,%2,%3}, {%4,%5,%6,%7}, {%8,%9}, {%0,%1,%2,%3};"
        : "+f"(c[0]), "+f"(c[1]), "+f"(c[2]), "+f"(c[3])
        : "r"(a[0]), "r"(a[1]), "r"(a[2]), "r"(a[3]), "r"(b0), "r"(b1));
}

__device__ __forceinline__ uint32_t smem_u32(const void* p) {
    uint32_t a;
    asm("{ .reg .u64 t; cvta.to.shared.u64 t, %1; cvt.u32.u64 %0, t; }"
        : "=r"(a) : "l"(p));
    return a;
}

__device__ __forceinline__ void ldsm4(uint32_t r[4], uint32_t addr) {
    asm volatile("ldmatrix.sync.aligned.m8n8.x4.shared.b16 {%0,%1,%2,%3}, [%4];"
        : "=r"(r[0]), "=r"(r[1]), "=r"(r[2]), "=r"(r[3]) : "r"(addr));
}
__device__ __forceinline__ void ldsm4t(uint32_t r[4], uint32_t addr) {
    asm volatile("ldmatrix.sync.aligned.m8n8.x4.trans.shared.b16 {%0,%1,%2,%3}, [%4];"
        : "=r"(r[0]), "=r"(r[1]), "=r"(r[2]), "=r"(r[3]) : "r"(addr));
}

__device__ __forceinline__ void cp16(uint32_t dst, const void* src) {
    asm volatile("cp.async.cg.shared.global [%0], [%1], 16;" :: "r"(dst), "l"(src) : "memory");
}
__device__ __forceinline__ void cp_commit() { asm volatile("cp.async.commit_group;" ::: "memory"); }
template<int N>
__device__ __forceinline__ void cp_wait() { asm volatile("cp.async.wait_group %0;" :: "n"(N) : "memory"); }

__device__ __forceinline__ uint32_t pack2(float x, float y) {
    __half2 h = __floats2half2_rn(x, y);
    return *(uint32_t*)&h;
}

// ==================== fused weight cvt fp16 + transpose (ONE launch) ====================
// 10240 tiles of 32x32: Wq/Wk/Wv/Wo (1024 each), W1 (4096), W2 (2048)
__global__ __launch_bounds__(256) void cvtw_all(
    const float* __restrict__ Wq, const float* __restrict__ Wk,
    const float* __restrict__ Wv, const float* __restrict__ Wo,
    const float* __restrict__ W1, const float* __restrict__ W2,
    __half* __restrict__ wh)
{
    __shared__ float tile[32][33];
    const int bid = blockIdx.x;
    const float* src; __half* dst; int K, N, t_;
    if (bid < 4096) {
        const int m = bid >> 10; t_ = bid & 1023;
        src = (m == 0) ? Wq : (m == 1) ? Wk : (m == 2) ? Wv : Wo;
        dst = wh + (size_t)m * 1048576;
        K = 1024; N = 1024;
    } else if (bid < 8192) {
        t_ = bid - 4096; src = W1; dst = wh + WOFF_1; K = 1024; N = 4096;
    } else {
        t_ = bid - 8192; src = W2; dst = wh + WOFF_2; K = 2048; N = 1024;
    }
    const int ntx = N >> 5;
    const int bn = (t_ % ntx) * 32, bk = (t_ / ntx) * 32;
    const int tx = threadIdx.x & 31, ty = threadIdx.x >> 5;
    #pragma unroll
    for (int r = 0; r < 4; ++r)
        tile[ty + 8*r][tx] = src[(size_t)(bk + ty + 8*r) * N + bn + tx];
    __syncthreads();
    #pragma unroll
    for (int r = 0; r < 4; ++r)
        dst[(size_t)(bn + ty + 8*r) * K + bk + tx] = __float2half_rn(tile[tx][ty + 8*r]);
}

// ==================== LayerNorm (fp32 in -> fp16 out) ====================
__global__ __launch_bounds__(256) void ln_kernel(const float* __restrict__ x,
                                                 const float* __restrict__ gamma,
                                                 const float* __restrict__ beta,
                                                 __half* __restrict__ out) {
    const int row = blockIdx.x;
    const int tid = threadIdx.x;
    const float4* xr = (const float4*)(x + (size_t)row * Dn);
    float4 v = xr[tid];
    float s  = v.x + v.y + v.z + v.w;
    float ss = v.x*v.x + v.y*v.y + v.z*v.z + v.w*v.w;
    #pragma unroll
    for (int off = 16; off > 0; off >>= 1) {
        s  += __shfl_xor_sync(0xffffffffu, s,  off);
        ss += __shfl_xor_sync(0xffffffffu, ss, off);
    }
    __shared__ float red[2][8];
    const int wid = tid >> 5, lid = tid & 31;
    if (lid == 0) { red[0][wid] = s; red[1][wid] = ss; }
    __syncthreads();
    __shared__ float smu, srstd;
    if (tid == 0) {
        float ts = 0.f, tss = 0.f;
        #pragma unroll
        for (int i = 0; i < 8; ++i) { ts += red[0][i]; tss += red[1][i]; }
        float mu  = ts * (1.0f / Dn);
        float var = tss * (1.0f / Dn) - mu * mu;
        smu = mu; srstd = rsqrtf(var + EPSV);
    }
    __syncthreads();
    const float mu = smu, rstd = srstd;
    float4 g = ((const float4*)gamma)[tid];
    float4 b = ((const float4*)beta)[tid];
    uint2 u;
    u.x = pack2(g.x * (v.x - mu) * rstd + b.x, g.y * (v.y - mu) * rstd + b.y);
    u.y = pack2(g.z * (v.z - mu) * rstd + b.z, g.w * (v.w - mu) * rstd + b.w);
    ((uint2*)(out + (size_t)row * Dn))[tid] = u;
}

// ==================== FP16 tensor GEMM, cp.async 3-stage + ldmatrix ====================
#define BM 128
#define BN 128
#define BKH 32
#define STAGES 3
#define TSH 56
#define TILE_BYTES (128*TSH*2)
#define GT_SMEM (STAGES*2*TILE_BYTES)   // 86016

template<bool RESID, bool OUT_HALF>
__device__ __forceinline__ void gemm_body(
    const __half* __restrict__ A, const __half* __restrict__ Bt,
    const float* __restrict__ R, void* __restrict__ Cv,
    int M_, int N_, int K_)
{
    extern __shared__ char smem[];
    const uint32_t sbase = smem_u32(smem);

    const int tid = threadIdx.x;
    const int bx = blockIdx.x, by = blockIdx.y;
    const int wid = tid >> 5, lane = tid & 31;
    const int wm = (wid >> 2) * 64, wn = (wid & 3) * 32;

    const int ld_row = tid >> 2;
    const int ld_ch  = tid & 3;

    const int lrow = lane & 15;
    const int lkh  = (lane >> 4) * 8;

    const int nt = K_ >> 5;
    int kload = 0;

    auto issue = [&](int kt, int st) {
        const uint32_t da = sbase + st*(2*TILE_BYTES);
        const uint32_t db = da + TILE_BYTES;
        cp16(da + (ld_row     )*(TSH*2) + ld_ch*16,
             &A[(size_t)(by*BM + ld_row     )*K_ + kt*BKH + ld_ch*8]);
        cp16(da + (ld_row + 64)*(TSH*2) + ld_ch*16,
             &A[(size_t)(by*BM + ld_row + 64)*K_ + kt*BKH + ld_ch*8]);
        cp16(db + (ld_row     )*(TSH*2) + ld_ch*16,
             &Bt[(size_t)(bx*BN + ld_row     )*K_ + kt*BKH + ld_ch*8]);
        cp16(db + (ld_row + 64)*(TSH*2) + ld_ch*16,
             &Bt[(size_t)(bx*BN + ld_row + 64)*K_ + kt*BKH + ld_ch*8]);
    };

    float acc[4][4][4];
    #pragma unroll
    for (int i = 0; i < 4; ++i)
        #pragma unroll
        for (int j = 0; j < 4; ++j)
            #pragma unroll
            for (int e = 0; e < 4; ++e) acc[i][j][e] = 0.f;

    issue(0, 0); cp_commit();
    issue(1, 1); cp_commit();
    kload = 2;

    int st = 0;
    for (int kt = 0; kt < nt; ++kt) {
        cp_wait<STAGES-2>();
        __syncthreads();
        const uint32_t sa = sbase + st*(2*TILE_BYTES);
        const uint32_t sb = sa + TILE_BYTES;
        #pragma unroll
        for (int kk = 0; kk < 2; ++kk) {
            uint32_t afr[4][4], bq[2][4];
            #pragma unroll
            for (int i = 0; i < 4; ++i)
                ldsm4(afr[i], sa + ((wm + i*16 + lrow)*TSH + kk*16 + lkh)*2);
            #pragma unroll
            for (int jj = 0; jj < 2; ++jj)
                ldsm4(bq[jj], sb + ((wn + jj*16 + lrow)*TSH + kk*16 + lkh)*2);
            #pragma unroll
            for (int i = 0; i < 4; ++i) {
                #pragma unroll
                for (int jj = 0; jj < 2; ++jj) {
                    mma_f16(acc[i][jj*2  ], afr[i], bq[jj][0], bq[jj][2]);
                    mma_f16(acc[i][jj*2+1], afr[i], bq[jj][1], bq[jj][3]);
                }
            }
        }
        if (kload < nt) {
            issue(kload, (st + 2 >= STAGES) ? st + 2 - STAGES : st + 2);
            ++kload;
        }
        cp_commit();
        if (++st == STAGES) st = 0;
    }

    // epilogue
    const int eg = lane >> 2, et = lane & 3;
    #pragma unroll
    for (int i = 0; i < 4; ++i) {
        const int row0 = by*BM + wm + i*16 + eg;
        const int row1 = row0 + 8;
        #pragma unroll
        for (int j = 0; j < 4; ++j) {
            const int col = bx*BN + wn + j*8 + et*2;
            if (OUT_HALF) {
                __half* C = (__half*)Cv;
                *(uint32_t*)&C[(size_t)row0*N_ + col] = pack2(acc[i][j][0], acc[i][j][1]);
                *(uint32_t*)&C[(size_t)row1*N_ + col] = pack2(acc[i][j][2], acc[i][j][3]);
            } else {
                float* C = (float*)Cv;
                float2 v0 = { acc[i][j][0], acc[i][j][1] };
                float2 v1 = { acc[i][j][2], acc[i][j][3] };
                if (RESID) {
                    float2 r0 = *(const float2*)&R[(size_t)row0*N_ + col];
                    float2 r1 = *(const float2*)&R[(size_t)row1*N_ + col];
                    v0.x += r0.x; v0.y += r0.y;
                    v1.x += r1.x; v1.y += r1.y;
                }
                *(float2*)&C[(size_t)row0*N_ + col] = v0;
                *(float2*)&C[(size_t)row1*N_ + col] = v1;
            }
        }
    }
}

template<bool RESID, bool OUT_HALF>
__global__ __launch_bounds__(256, 2) void gemm_k(
    const __half* __restrict__ A, const __half* __restrict__ Bt,
    const float* __restrict__ R, void* __restrict__ Cv,
    int M_, int N_, int K_)
{
    gemm_body<RESID, OUT_HALF>(A, Bt, R, Cv, M_, N_, K_);
}

__global__ __launch_bounds__(256, 2) void gemm_qkv(
    const __half* __restrict__ A, const __half* __restrict__ W,
    __half* __restrict__ q, __half* __restrict__ k, __half* __restrict__ v)
{
    const int z = blockIdx.z;
    const __half* Bt = W + (z == 0 ? WOFF_Q : z == 1 ? WOFF_K : WOFF_V);
    __half* C = (z == 0) ? q : (z == 1) ? k : v;
    gemm_body<false, true>(A, Bt, nullptr, C, Mn, Dn, Dn);
}

// ==================== GLU (fp16 h -> fp16 glu) ====================
__global__ __launch_bounds__(256) void glu_kernel(const __half* __restrict__ h,
                                                  __half* __restrict__ g) {
    const int idx = blockIdx.x * blockDim.x + threadIdx.x;
    const int row = idx >> 9;
    const int c4  = idx & 511;
    uint2 lu = *(const uint2*)&h[(size_t)row*DFF + c4*4];
    uint2 ru = *(const uint2*)&h[(size_t)row*DFF + DG + c4*4];
    float2 l0 = __half22float2(*(__half2*)&lu.x);
    float2 l1 = __half22float2(*(__half2*)&lu.y);
    float2 r0 = __half22float2(*(__half2*)&ru.x);
    float2 r1 = __half22float2(*(__half2*)&ru.y);
    uint2 u;
    u.x = pack2(l0.x / (1.f + __expf(-r0.x)), l0.y / (1.f + __expf(-r0.y)));
    u.y = pack2(l1.x / (1.f + __expf(-r1.x)), l1.y / (1.f + __expf(-r1.y)));
    *(uint2*)&g[(size_t)row*DG + c4*4] = u;
}

// ==================== causal flash attention (fp16 MMA, double-buffered K/V) ====================
#define KVS 72
#define KV_STAGE_BYTES (2*64*KVS*2)       // K+V one stage: 18432
#define ATTN_SMEM (2*KV_STAGE_BYTES)      // 36864

__global__ __launch_bounds__(128) void attn_f16(
    const __half* __restrict__ Q, const __half* __restrict__ K,
    const __half* __restrict__ V, const int* __restrict__ mask,
    __half* __restrict__ O) {
    extern __shared__ __half smh[];
    const uint32_t sm0 = smem_u32(smh);
    __shared__ int msk[2][64];

    const int qt = blockIdx.x, h = blockIdx.y, b = blockIdx.z;
    const int tid = threadIdx.x;
    const int wid = tid >> 5, lane = tid & 31;
    const int g = lane >> 2, t = lane & 3;
    const int lrow = lane & 15;
    const int lkh  = (lane >> 4) * 8;

    // Q fragments in registers
    const __half* Qb = Q + ((size_t)(b*Sn + qt*64 + wid*16))*Dn + h*DHn;
    uint32_t qa[4][4];
    #pragma unroll
    for (int ks = 0; ks < 4; ++ks) {
        qa[ks][0] = *(const uint32_t*)&Qb[(size_t)(g    )*Dn + ks*16 + 2*t];
        qa[ks][1] = *(const uint32_t*)&Qb[(size_t)(g + 8)*Dn + ks*16 + 2*t];
        qa[ks][2] = *(const uint32_t*)&Qb[(size_t)(g    )*Dn + ks*16 + 8 + 2*t];
        qa[ks][3] = *(const uint32_t*)&Qb[(size_t)(g + 8)*Dn + ks*16 + 8 + 2*t];
    }

    auto load_kv = [&](int kt, int st) {
        const uint32_t ks_u = sm0 + st*KV_STAGE_BYTES;
        const uint32_t vs_u = ks_u + 64*KVS*2;
        const __half* Kb = K + (size_t)(b*Sn + kt*64)*Dn + h*DHn;
        const __half* Vb = V + (size_t)(b*Sn + kt*64)*Dn + h*DHn;
        #pragma unroll
        for (int c = 0; c < 4; ++c) {
            const int idx = tid + c*128;
            const int rr = idx >> 3, ch = idx & 7;
            cp16(ks_u + rr*(KVS*2) + ch*16, Kb + (size_t)rr*Dn + ch*8);
            cp16(vs_u + rr*(KVS*2) + ch*16, Vb + (size_t)rr*Dn + ch*8);
        }
        if (tid < 64) msk[st][tid] = mask[b*Sn + kt*64 + tid];
    };

    float o[8][4];
    #pragma unroll
    for (int j = 0; j < 8; ++j)
        #pragma unroll
        for (int e = 0; e < 4; ++e) o[j][e] = 0.f;
    float m0 = -1e30f, m1 = -1e30f, l0 = 0.f, l1 = 0.f;
    const float scale = 0.125f;

    const int rowg0 = qt*64 + wid*16 + g;
    const int rowg1 = rowg0 + 8;

    // prologue: stage kt=0 (buf0) and kt=1 (buf1)
    load_kv(0, 0); cp_commit();
    if (qt >= 1) load_kv(1, 1);
    cp_commit();

    int buf = 0;
    for (int kt = 0; kt <= qt; ++kt) {
        cp_wait<1>();          // group kt complete (groups numbered == kt)
        __syncthreads();
        const uint32_t ks_u = sm0 + buf*KV_STAGE_BYTES;
        const uint32_t vs_u = ks_u + 64*KVS*2;

        // S = Q @ K^T
        float sc[8][4];
        #pragma unroll
        for (int j = 0; j < 8; ++j)
            #pragma unroll
            for (int e = 0; e < 4; ++e) sc[j][e] = 0.f;
        #pragma unroll
        for (int ks = 0; ks < 4; ++ks) {
            #pragma unroll
            for (int jj = 0; jj < 4; ++jj) {
                uint32_t bq[4];
                ldsm4(bq, ks_u + ((jj*16 + lrow)*KVS + ks*16 + lkh)*2);
                mma_f16(sc[jj*2  ], qa[ks], bq[0], bq[2]);
                mma_f16(sc[jj*2+1], qa[ks], bq[1], bq[3]);
            }
        }

        // scale + causal + key mask
        #pragma unroll
        for (int j = 0; j < 8; ++j) {
            #pragma unroll
            for (int e = 0; e < 4; ++e) {
                const int cl  = j*8 + t*2 + (e & 1);
                const int kg  = kt*64 + cl;
                const int row = (e < 2) ? rowg0 : rowg1;
                const bool ok = (kg <= row) && (msk[buf][cl] != 0);
                sc[j][e] = ok ? sc[j][e] * scale : -1e30f;
            }
        }

        // online softmax
        float rm0 = -1e30f, rm1 = -1e30f;
        #pragma unroll
        for (int j = 0; j < 8; ++j) {
            rm0 = fmaxf(rm0, fmaxf(sc[j][0], sc[j][1]));
            rm1 = fmaxf(rm1, fmaxf(sc[j][2], sc[j][3]));
        }
        rm0 = fmaxf(rm0, __shfl_xor_sync(0xffffffffu, rm0, 1));
        rm0 = fmaxf(rm0, __shfl_xor_sync(0xffffffffu, rm0, 2));
        rm1 = fmaxf(rm1, __shfl_xor_sync(0xffffffffu, rm1, 1));
        rm1 = fmaxf(rm1, __shfl_xor_sync(0xffffffffu, rm1, 2));
        const float mn0 = fmaxf(m0, rm0), mn1 = fmaxf(m1, rm1);
        const float al0 = __expf(m0 - mn0), al1 = __expf(m1 - mn1);
        float s0 = 0.f, s1 = 0.f;
        #pragma unroll
        for (int j = 0; j < 8; ++j) {
            sc[j][0] = __expf(sc[j][0] - mn0);
            sc[j][1] = __expf(sc[j][1] - mn0);
            sc[j][2] = __expf(sc[j][2] - mn1);
            sc[j][3] = __expf(sc[j][3] - mn1);
            s0 += sc[j][0] + sc[j][1];
            s1 += sc[j][2] + sc[j][3];
        }
        s0 += __shfl_xor_sync(0xffffffffu, s0, 1);
        s0 += __shfl_xor_sync(0xffffffffu, s0, 2);
        s1 += __shfl_xor_sync(0xffffffffu, s1, 1);
        s1 += __shfl_xor_sync(0xffffffffu, s1, 2);
        l0 = l0 * al0 + s0;  m0 = mn0;
        l1 = l1 * al1 + s1;  m1 = mn1;
        #pragma unroll
        for (int j = 0; j < 8; ++j) {
            o[j][0] *= al0; o[j][1] *= al0;
            o[j][2] *= al1; o[j][3] *= al1;
        }

        // O += P @ V (P fragments are direct repacks of sc)
        #pragma unroll
        for (int ks = 0; ks < 4; ++ks) {
            uint32_t pa[4];
            pa[0] = pack2(sc[2*ks  ][0], sc[2*ks  ][1]);
            pa[1] = pack2(sc[2*ks  ][2], sc[2*ks  ][3]);
            pa[2] = pack2(sc[2*ks+1][0], sc[2*ks+1][1]);
            pa[3] = pack2(sc[2*ks+1][2], sc[2*ks+1][3]);
            #pragma unroll
            for (int jj = 0; jj < 4; ++jj) {
                uint32_t bq[4];
                ldsm4t(bq, vs_u + ((ks*16 + lrow)*KVS + jj*16 + lkh)*2);
                mma_f16(o[jj*2  ], pa, bq[0], bq[1]);
                mma_f16(o[jj*2+1], pa, bq[2], bq[3]);
            }
        }

        __syncthreads();               // all warps done reading buf
        if (kt + 2 <= qt) load_kv(kt + 2, buf);
        cp_commit();                   // keep group numbering aligned with kt
        buf ^= 1;
    }

    const float i0 = 1.f / l0, i1 = 1.f / l1;
    __half* Ob = O + ((size_t)(b*Sn + qt*64 + wid*16))*Dn + h*DHn;
    #pragma unroll
    for (int j = 0; j < 8; ++j) {
        *(uint32_t*)&Ob[(size_t)(g    )*Dn + j*8 + t*2] = pack2(o[j][0]*i0, o[j][1]*i0);
        *(uint32_t*)&Ob[(size_t)(g + 8)*Dn + j*8 + t*2] = pack2(o[j][2]*i1, o[j][3]*i1);
    }
}

// ==================== launch ====================
extern "C" void kernel_launch(void* const* d_in, const int* in_sizes, int n_in,
                              void* d_out, int out_size) {
    const float* x     = (const float*)d_in[0];
    const int*   amask = (const int*)  d_in[1];
    const float* Wq    = (const float*)d_in[2];
    const float* Wk    = (const float*)d_in[3];
    const float* Wv    = (const float*)d_in[4];
    const float* Wo    = (const float*)d_in[5];
    const float* W1    = (const float*)d_in[6];
    const float* W2    = (const float*)d_in[7];
    const float* gamma1= (const float*)d_in[8];
    const float* beta1 = (const float*)d_in[9];
    const float* gamma2= (const float*)d_in[10];
    const float* beta2 = (const float*)d_in[11];
    float* out = (float*)d_out;

    __half *xn1, *q, *k, *v, *attn, *xn2, *glu, *wh, *hbuf;
    float *x1;
    cudaGetSymbolAddress((void**)&xn1,  g_xn1);
    cudaGetSymbolAddress((void**)&q,    g_q);
    cudaGetSymbolAddress((void**)&k,    g_k);
    cudaGetSymbolAddress((void**)&v,    g_v);
    cudaGetSymbolAddress((void**)&attn, g_attn);
    cudaGetSymbolAddress((void**)&x1,   g_x1);
    cudaGetSymbolAddress((void**)&xn2,  g_xn2);
    cudaGetSymbolAddress((void**)&hbuf, g_h);
    cudaGetSymbolAddress((void**)&glu,  g_glu);
    cudaGetSymbolAddress((void**)&wh,   g_wh);

    cudaFuncSetAttribute(attn_f16, cudaFuncAttributeMaxDynamicSharedMemorySize, ATTN_SMEM);
    cudaFuncSetAttribute(gemm_qkv, cudaFuncAttributeMaxDynamicSharedMemorySize, GT_SMEM);
    cudaFuncSetAttribute((const void*)gemm_k<false,true>,  cudaFuncAttributeMaxDynamicSharedMemorySize, GT_SMEM);
    cudaFuncSetAttribute((const void*)gemm_k<true,false>,  cudaFuncAttributeMaxDynamicSharedMemorySize, GT_SMEM);

    // 0. fused weight convert+transpose (single launch)
    cvtw_all<<<10240, 256>>>(Wq, Wk, Wv, Wo, W1, W2, wh);

    // 1. LN1 -> fp16
    ln_kernel<<<Mn, 256>>>(x, gamma1, beta1, xn1);

    // 2. fused Q,K,V projections -> fp16
    dim3 gQKV(Dn/BN, Mn/BM, 3);
    gemm_qkv<<<gQKV, 256, GT_SMEM>>>(xn1, wh, q, k, v);

    // 3. causal attention -> fp16 (double-buffered K/V)
    dim3 gA(Sn/64, Hn, Bn);
    attn_f16<<<gA, 128, ATTN_SMEM>>>(q, k, v, amask, attn);

    // 4. output projection + residual -> fp32 x1
    dim3 gD(Dn/BN, Mn/BM);
    gemm_k<true,false><<<gD, 256, GT_SMEM>>>(attn, wh + WOFF_O, x, x1, Mn, Dn, Dn);

    // 5. LN2 -> fp16
    ln_kernel<<<Mn, 256>>>(x1, gamma2, beta2, xn2);

    // 6. W1 (N=4096) -> fp16 h
    dim3 gF(DFF/BN, Mn/BM);
    gemm_k<false,true><<<gF, 256, GT_SMEM>>>(xn2, wh + WOFF_1, nullptr, hbuf, Mn, DFF, Dn);

    // 7. GLU -> fp16
    glu_kernel<<<(Mn*DG/4)/256, 256>>>(hbuf, glu);

    // 8. W2 + residual -> fp32 out
    gemm_k<true,false><<<gD, 256, GT_SMEM>>>(glu, wh + WOFF_2, x1, out, Mn, Dn, DG);
}

// round 9
// speedup vs baseline: 1.7958x; 1.0157x over previous
#include <cuda_runtime.h>
#include <cuda_fp16.h>
#include <math.h>
#include <stdint.h>

// Problem constants
#define Bn   2
#define Sn   2048
#define Dn   1024
#define Hn   16
#define DHn  64
#define Mn   (Bn*Sn)          // 4096 rows
#define DFF  (4*Dn)           // 4096
#define DG   (2*Dn)           // 2048
#define EPSV 1e-5f

// -------------------- scratch (device globals; no allocation) --------------------
__device__ __half g_xn1 [Mn*Dn];
__device__ __half g_q   [Mn*Dn];
__device__ __half g_k   [Mn*Dn];
__device__ __half g_v   [Mn*Dn];
__device__ __half g_attn[Mn*Dn];
__device__ float  g_x1  [Mn*Dn];
__device__ __half g_xn2 [Mn*Dn];
__device__ __half g_h   [Mn*DFF];
__device__ __half g_glu [Mn*DG];
__device__ __half g_wh  [10485760];  // fp16 TRANSPOSED weights [N][K]

#define WOFF_Q  0
#define WOFF_K  1048576
#define WOFF_V  2097152
#define WOFF_O  3145728
#define WOFF_1  4194304
#define WOFF_2  8388608

// -------------------- helpers --------------------
__device__ __forceinline__ void mma_f16(float c[4], const uint32_t a[4],
                                        uint32_t b0, uint32_t b1) {
    asm volatile(
        "mma.sync.aligned.m16n8k16.row.col.f32.f16.f16.f32 "
        "{%0,%1,%2,%3}, {%4,%5,%6,%7}, {%8,%9}, {%0,%1,%2,%3};"
        : "+f"(c[0]), "+f"(c[1]), "+f"(c[2]), "+f"(c[3])
        : "r"(a[0]), "r"(a[1]), "r"(a[2]), "r"(a[3]), "r"(b0), "r"(b1));
}

__device__ __forceinline__ uint32_t smem_u32(const void* p) {
    uint32_t a;
    asm("{ .reg .u64 t; cvta.to.shared.u64 t, %1; cvt.u32.u64 %0, t; }"
        : "=r"(a) : "l"(p));
    return a;
}

__device__ __forceinline__ void ldsm4(uint32_t r[4], uint32_t addr) {
    asm volatile("ldmatrix.sync.aligned.m8n8.x4.shared.b16 {%0,%1,%2,%3}, [%4];"
        : "=r"(r[0]), "=r"(r[1]), "=r"(r[2]), "=r"(r[3]) : "r"(addr));
}
__device__ __forceinline__ void ldsm4t(uint32_t r[4], uint32_t addr) {
    asm volatile("ldmatrix.sync.aligned.m8n8.x4.trans.shared.b16 {%0,%1,%2,%3}, [%4];"
        : "=r"(r[0]), "=r"(r[1]), "=r"(r[2]), "=r"(r[3]) : "r"(addr));
}

__device__ __forceinline__ void cp16(uint32_t dst, const void* src) {
    asm volatile("cp.async.cg.shared.global [%0], [%1], 16;" :: "r"(dst), "l"(src) : "memory");
}
__device__ __forceinline__ void cp_commit() { asm volatile("cp.async.commit_group;" ::: "memory"); }
template<int N>
__device__ __forceinline__ void cp_wait() { asm volatile("cp.async.wait_group %0;" :: "n"(N) : "memory"); }

__device__ __forceinline__ uint32_t pack2(float x, float y) {
    __half2 h = __floats2half2_rn(x, y);
    return *(uint32_t*)&h;
}

// ==================== fused weight cvt fp16 + transpose (ONE launch) ====================
__global__ __launch_bounds__(256) void cvtw_all(
    const float* __restrict__ Wq, const float* __restrict__ Wk,
    const float* __restrict__ Wv, const float* __restrict__ Wo,
    const float* __restrict__ W1, const float* __restrict__ W2,
    __half* __restrict__ wh)
{
    __shared__ float tile[32][33];
    const int bid = blockIdx.x;
    const float* src; __half* dst; int K, N, t_;
    if (bid < 4096) {
        const int m = bid >> 10; t_ = bid & 1023;
        src = (m == 0) ? Wq : (m == 1) ? Wk : (m == 2) ? Wv : Wo;
        dst = wh + (size_t)m * 1048576;
        K = 1024; N = 1024;
    } else if (bid < 8192) {
        t_ = bid - 4096; src = W1; dst = wh + WOFF_1; K = 1024; N = 4096;
    } else {
        t_ = bid - 8192; src = W2; dst = wh + WOFF_2; K = 2048; N = 1024;
    }
    const int ntx = N >> 5;
    const int bn = (t_ % ntx) * 32, bk = (t_ / ntx) * 32;
    const int tx = threadIdx.x & 31, ty = threadIdx.x >> 5;
    #pragma unroll
    for (int r = 0; r < 4; ++r)
        tile[ty + 8*r][tx] = src[(size_t)(bk + ty + 8*r) * N + bn + tx];
    __syncthreads();
    #pragma unroll
    for (int r = 0; r < 4; ++r)
        dst[(size_t)(bn + ty + 8*r) * K + bk + tx] = __float2half_rn(tile[tx][ty + 8*r]);
}

// ==================== LayerNorm (fp32 in -> fp16 out) ====================
__global__ __launch_bounds__(256) void ln_kernel(const float* __restrict__ x,
                                                 const float* __restrict__ gamma,
                                                 const float* __restrict__ beta,
                                                 __half* __restrict__ out) {
    const int row = blockIdx.x;
    const int tid = threadIdx.x;
    const float4* xr = (const float4*)(x + (size_t)row * Dn);
    float4 v = xr[tid];
    float s  = v.x + v.y + v.z + v.w;
    float ss = v.x*v.x + v.y*v.y + v.z*v.z + v.w*v.w;
    #pragma unroll
    for (int off = 16; off > 0; off >>= 1) {
        s  += __shfl_xor_sync(0xffffffffu, s,  off);
        ss += __shfl_xor_sync(0xffffffffu, ss, off);
    }
    __shared__ float red[2][8];
    const int wid = tid >> 5, lid = tid & 31;
    if (lid == 0) { red[0][wid] = s; red[1][wid] = ss; }
    __syncthreads();
    __shared__ float smu, srstd;
    if (tid == 0) {
        float ts = 0.f, tss = 0.f;
        #pragma unroll
        for (int i = 0; i < 8; ++i) { ts += red[0][i]; tss += red[1][i]; }
        float mu  = ts * (1.0f / Dn);
        float var = tss * (1.0f / Dn) - mu * mu;
        smu = mu; srstd = rsqrtf(var + EPSV);
    }
    __syncthreads();
    const float mu = smu, rstd = srstd;
    float4 g = ((const float4*)gamma)[tid];
    float4 b = ((const float4*)beta)[tid];
    uint2 u;
    u.x = pack2(g.x * (v.x - mu) * rstd + b.x, g.y * (v.y - mu) * rstd + b.y);
    u.y = pack2(g.z * (v.z - mu) * rstd + b.z, g.w * (v.w - mu) * rstd + b.w);
    ((uint2*)(out + (size_t)row * Dn))[tid] = u;
}

// ==================== FP16 tensor GEMM, cp.async 3-stage + ldmatrix ====================
#define BM 128
#define BN 128
#define BKH 32
#define STAGES 3
#define TSH 56
#define TILE_BYTES (128*TSH*2)
#define GT_SMEM (STAGES*2*TILE_BYTES)   // 86016

template<bool RESID, bool OUT_HALF>
__device__ __forceinline__ void gemm_body(
    const __half* __restrict__ A, const __half* __restrict__ Bt,
    const float* __restrict__ R, void* __restrict__ Cv,
    int M_, int N_, int K_, float oscale)
{
    extern __shared__ char smem[];
    const uint32_t sbase = smem_u32(smem);

    const int tid = threadIdx.x;
    const int bx = blockIdx.x, by = blockIdx.y;
    const int wid = tid >> 5, lane = tid & 31;
    const int wm = (wid >> 2) * 64, wn = (wid & 3) * 32;

    const int ld_row = tid >> 2;
    const int ld_ch  = tid & 3;

    const int lrow = lane & 15;
    const int lkh  = (lane >> 4) * 8;

    const int nt = K_ >> 5;
    int kload = 0;

    auto issue = [&](int kt, int st) {
        const uint32_t da = sbase + st*(2*TILE_BYTES);
        const uint32_t db = da + TILE_BYTES;
        cp16(da + (ld_row     )*(TSH*2) + ld_ch*16,
             &A[(size_t)(by*BM + ld_row     )*K_ + kt*BKH + ld_ch*8]);
        cp16(da + (ld_row + 64)*(TSH*2) + ld_ch*16,
             &A[(size_t)(by*BM + ld_row + 64)*K_ + kt*BKH + ld_ch*8]);
        cp16(db + (ld_row     )*(TSH*2) + ld_ch*16,
             &Bt[(size_t)(bx*BN + ld_row     )*K_ + kt*BKH + ld_ch*8]);
        cp16(db + (ld_row + 64)*(TSH*2) + ld_ch*16,
             &Bt[(size_t)(bx*BN + ld_row + 64)*K_ + kt*BKH + ld_ch*8]);
    };

    float acc[4][4][4];
    #pragma unroll
    for (int i = 0; i < 4; ++i)
        #pragma unroll
        for (int j = 0; j < 4; ++j)
            #pragma unroll
            for (int e = 0; e < 4; ++e) acc[i][j][e] = 0.f;

    issue(0, 0); cp_commit();
    issue(1, 1); cp_commit();
    kload = 2;

    int st = 0;
    for (int kt = 0; kt < nt; ++kt) {
        cp_wait<STAGES-2>();
        __syncthreads();
        const uint32_t sa = sbase + st*(2*TILE_BYTES);
        const uint32_t sb = sa + TILE_BYTES;
        #pragma unroll
        for (int kk = 0; kk < 2; ++kk) {
            uint32_t afr[4][4], bq[2][4];
            #pragma unroll
            for (int i = 0; i < 4; ++i)
                ldsm4(afr[i], sa + ((wm + i*16 + lrow)*TSH + kk*16 + lkh)*2);
            #pragma unroll
            for (int jj = 0; jj < 2; ++jj)
                ldsm4(bq[jj], sb + ((wn + jj*16 + lrow)*TSH + kk*16 + lkh)*2);
            #pragma unroll
            for (int i = 0; i < 4; ++i) {
                #pragma unroll
                for (int jj = 0; jj < 2; ++jj) {
                    mma_f16(acc[i][jj*2  ], afr[i], bq[jj][0], bq[jj][2]);
                    mma_f16(acc[i][jj*2+1], afr[i], bq[jj][1], bq[jj][3]);
                }
            }
        }
        if (kload < nt) {
            issue(kload, (st + 2 >= STAGES) ? st + 2 - STAGES : st + 2);
            ++kload;
        }
        cp_commit();
        if (++st == STAGES) st = 0;
    }

    // epilogue
    const int eg = lane >> 2, et = lane & 3;
    #pragma unroll
    for (int i = 0; i < 4; ++i) {
        const int row0 = by*BM + wm + i*16 + eg;
        const int row1 = row0 + 8;
        #pragma unroll
        for (int j = 0; j < 4; ++j) {
            const int col = bx*BN + wn + j*8 + et*2;
            if (OUT_HALF) {
                __half* C = (__half*)Cv;
                *(uint32_t*)&C[(size_t)row0*N_ + col] =
                    pack2(acc[i][j][0]*oscale, acc[i][j][1]*oscale);
                *(uint32_t*)&C[(size_t)row1*N_ + col] =
                    pack2(acc[i][j][2]*oscale, acc[i][j][3]*oscale);
            } else {
                float* C = (float*)Cv;
                float2 v0 = { acc[i][j][0], acc[i][j][1] };
                float2 v1 = { acc[i][j][2], acc[i][j][3] };
                if (RESID) {
                    float2 r0 = *(const float2*)&R[(size_t)row0*N_ + col];
                    float2 r1 = *(const float2*)&R[(size_t)row1*N_ + col];
                    v0.x += r0.x; v0.y += r0.y;
                    v1.x += r1.x; v1.y += r1.y;
                }
                *(float2*)&C[(size_t)row0*N_ + col] = v0;
                *(float2*)&C[(size_t)row1*N_ + col] = v1;
            }
        }
    }
}

template<bool RESID, bool OUT_HALF>
__global__ __launch_bounds__(256, 2) void gemm_k(
    const __half* __restrict__ A, const __half* __restrict__ Bt,
    const float* __restrict__ R, void* __restrict__ Cv,
    int M_, int N_, int K_)
{
    gemm_body<RESID, OUT_HALF>(A, Bt, R, Cv, M_, N_, K_, 1.0f);
}

// fused QKV; q output pre-scaled by 1/sqrt(DH)=0.125 (exact power of 2)
__global__ __launch_bounds__(256, 2) void gemm_qkv(
    const __half* __restrict__ A, const __half* __restrict__ W,
    __half* __restrict__ q, __half* __restrict__ k, __half* __restrict__ v)
{
    const int z = blockIdx.z;
    const __half* Bt = W + (z == 0 ? WOFF_Q : z == 1 ? WOFF_K : WOFF_V);
    __half* C = (z == 0) ? q : (z == 1) ? k : v;
    gemm_body<false, true>(A, Bt, nullptr, C, Mn, Dn, Dn, z == 0 ? 0.125f : 1.0f);
}

// ==================== GLU (fp16 h -> fp16 glu) ====================
__global__ __launch_bounds__(256) void glu_kernel(const __half* __restrict__ h,
                                                  __half* __restrict__ g) {
    const int idx = blockIdx.x * blockDim.x + threadIdx.x;
    const int row = idx >> 9;
    const int c4  = idx & 511;
    uint2 lu = *(const uint2*)&h[(size_t)row*DFF + c4*4];
    uint2 ru = *(const uint2*)&h[(size_t)row*DFF + DG + c4*4];
    float2 l0 = __half22float2(*(__half2*)&lu.x);
    float2 l1 = __half22float2(*(__half2*)&lu.y);
    float2 r0 = __half22float2(*(__half2*)&ru.x);
    float2 r1 = __half22float2(*(__half2*)&ru.y);
    uint2 u;
    u.x = pack2(l0.x / (1.f + __expf(-r0.x)), l0.y / (1.f + __expf(-r0.y)));
    u.y = pack2(l1.x / (1.f + __expf(-r1.x)), l1.y / (1.f + __expf(-r1.y)));
    *(uint2*)&g[(size_t)row*DG + c4*4] = u;
}

// ==================== causal flash attention (fp16 MMA, dbl-buffered, mask fast path) ====================
#define KVS 72
#define KV_STAGE_BYTES (2*64*KVS*2)
#define ATTN_SMEM (2*KV_STAGE_BYTES)      // 36864

__global__ __launch_bounds__(128) void attn_f16(
    const __half* __restrict__ Q, const __half* __restrict__ K,
    const __half* __restrict__ V, const int* __restrict__ mask,
    __half* __restrict__ O) {
    extern __shared__ __half smh[];
    const uint32_t sm0 = smem_u32(smh);
    __shared__ uint32_t mbits[2][2];     // [stage][half]: ballot of mask!=0

    const int qt = gridDim.x - 1 - blockIdx.x;   // heavy blocks first
    const int h = blockIdx.y, b = blockIdx.z;
    const int tid = threadIdx.x;
    const int wid = tid >> 5, lane = tid & 31;
    const int g = lane >> 2, t = lane & 3;
    const int lrow = lane & 15;
    const int lkh  = (lane >> 4) * 8;

    // Q fragments (pre-scaled by 0.125 in QKV epilogue)
    const __half* Qb = Q + ((size_t)(b*Sn + qt*64 + wid*16))*Dn + h*DHn;
    uint32_t qa[4][4];
    #pragma unroll
    for (int ks = 0; ks < 4; ++ks) {
        qa[ks][0] = *(const uint32_t*)&Qb[(size_t)(g    )*Dn + ks*16 + 2*t];
        qa[ks][1] = *(const uint32_t*)&Qb[(size_t)(g + 8)*Dn + ks*16 + 2*t];
        qa[ks][2] = *(const uint32_t*)&Qb[(size_t)(g    )*Dn + ks*16 + 8 + 2*t];
        qa[ks][3] = *(const uint32_t*)&Qb[(size_t)(g + 8)*Dn + ks*16 + 8 + 2*t];
    }

    auto load_kv = [&](int kt, int st) {
        const uint32_t ks_u = sm0 + st*KV_STAGE_BYTES;
        const uint32_t vs_u = ks_u + 64*KVS*2;
        const __half* Kb = K + (size_t)(b*Sn + kt*64)*Dn + h*DHn;
        const __half* Vb = V + (size_t)(b*Sn + kt*64)*Dn + h*DHn;
        #pragma unroll
        for (int c = 0; c < 4; ++c) {
            const int idx = tid + c*128;
            const int rr = idx >> 3, ch = idx & 7;
            cp16(ks_u + rr*(KVS*2) + ch*16, Kb + (size_t)rr*Dn + ch*8);
            cp16(vs_u + rr*(KVS*2) + ch*16, Vb + (size_t)rr*Dn + ch*8);
        }
        if (tid < 64) {
            const int val = mask[b*Sn + kt*64 + tid];
            const unsigned bal = __ballot_sync(0xffffffffu, val != 0);
            if ((tid & 31) == 0) mbits[st][tid >> 5] = bal;
        }
    };

    float o[8][4];
    #pragma unroll
    for (int j = 0; j < 8; ++j)
        #pragma unroll
        for (int e = 0; e < 4; ++e) o[j][e] = 0.f;
    float m0 = -1e30f, m1 = -1e30f, l0 = 0.f, l1 = 0.f;

    const int rowg0 = qt*64 + wid*16 + g;
    const int rowg1 = rowg0 + 8;

    load_kv(0, 0); cp_commit();
    if (qt >= 1) load_kv(1, 1);
    cp_commit();

    int buf = 0;
    for (int kt = 0; kt <= qt; ++kt) {
        cp_wait<1>();
        __syncthreads();
        const uint32_t ks_u = sm0 + buf*KV_STAGE_BYTES;
        const uint32_t vs_u = ks_u + 64*KVS*2;

        // S = Q @ K^T (already scaled via Q)
        float sc[8][4];
        #pragma unroll
        for (int j = 0; j < 8; ++j)
            #pragma unroll
            for (int e = 0; e < 4; ++e) sc[j][e] = 0.f;
        #pragma unroll
        for (int ks = 0; ks < 4; ++ks) {
            #pragma unroll
            for (int jj = 0; jj < 4; ++jj) {
                uint32_t bq[4];
                ldsm4(bq, ks_u + ((jj*16 + lrow)*KVS + ks*16 + lkh)*2);
                mma_f16(sc[jj*2  ], qa[ks], bq[0], bq[2]);
                mma_f16(sc[jj*2+1], qa[ks], bq[1], bq[3]);
            }
        }

        // masking: skip entirely on non-diagonal tiles with all-ones key mask
        const uint32_t mb0 = mbits[buf][0], mb1 = mbits[buf][1];
        const bool need_mask = (kt == qt) || ((mb0 & mb1) != 0xffffffffu);
        if (need_mask) {
            #pragma unroll
            for (int j = 0; j < 8; ++j) {
                #pragma unroll
                for (int e = 0; e < 4; ++e) {
                    const int cl  = j*8 + t*2 + (e & 1);
                    const int kg  = kt*64 + cl;
                    const int row = (e < 2) ? rowg0 : rowg1;
                    const bool km = (cl < 32) ? ((mb0 >> cl) & 1u) : ((mb1 >> (cl - 32)) & 1u);
                    const bool ok = (kg <= row) && km;
                    sc[j][e] = ok ? sc[j][e] : -1e30f;
                }
            }
        }

        // online softmax
        float rm0 = -1e30f, rm1 = -1e30f;
        #pragma unroll
        for (int j = 0; j < 8; ++j) {
            rm0 = fmaxf(rm0, fmaxf(sc[j][0], sc[j][1]));
            rm1 = fmaxf(rm1, fmaxf(sc[j][2], sc[j][3]));
        }
        rm0 = fmaxf(rm0, __shfl_xor_sync(0xffffffffu, rm0, 1));
        rm0 = fmaxf(rm0, __shfl_xor_sync(0xffffffffu, rm0, 2));
        rm1 = fmaxf(rm1, __shfl_xor_sync(0xffffffffu, rm1, 1));
        rm1 = fmaxf(rm1, __shfl_xor_sync(0xffffffffu, rm1, 2));
        const float mn0 = fmaxf(m0, rm0), mn1 = fmaxf(m1, rm1);
        const float al0 = __expf(m0 - mn0), al1 = __expf(m1 - mn1);
        float s0 = 0.f, s1 = 0.f;
        #pragma unroll
        for (int j = 0; j < 8; ++j) {
            sc[j][0] = __expf(sc[j][0] - mn0);
            sc[j][1] = __expf(sc[j][1] - mn0);
            sc[j][2] = __expf(sc[j][2] - mn1);
            sc[j][3] = __expf(sc[j][3] - mn1);
            s0 += sc[j][0] + sc[j][1];
            s1 += sc[j][2] + sc[j][3];
        }
        s0 += __shfl_xor_sync(0xffffffffu, s0, 1);
        s0 += __shfl_xor_sync(0xffffffffu, s0, 2);
        s1 += __shfl_xor_sync(0xffffffffu, s1, 1);
        s1 += __shfl_xor_sync(0xffffffffu, s1, 2);
        l0 = l0 * al0 + s0;  m0 = mn0;
        l1 = l1 * al1 + s1;  m1 = mn1;
        #pragma unroll
        for (int j = 0; j < 8; ++j) {
            o[j][0] *= al0; o[j][1] *= al0;
            o[j][2] *= al1; o[j][3] *= al1;
        }

        // O += P @ V (P fragments are direct repacks of sc)
        #pragma unroll
        for (int ks = 0; ks < 4; ++ks) {
            uint32_t pa[4];
            pa[0] = pack2(sc[2*ks  ][0], sc[2*ks  ][1]);
            pa[1] = pack2(sc[2*ks  ][2], sc[2*ks  ][3]);
            pa[2] = pack2(sc[2*ks+1][0], sc[2*ks+1][1]);
            pa[3] = pack2(sc[2*ks+1][2], sc[2*ks+1][3]);
            #pragma unroll
            for (int jj = 0; jj < 4; ++jj) {
                uint32_t bq[4];
                ldsm4t(bq, vs_u + ((ks*16 + lrow)*KVS + jj*16 + lkh)*2);
                mma_f16(o[jj*2  ], pa, bq[0], bq[1]);
                mma_f16(o[jj*2+1], pa, bq[2], bq[3]);
            }
        }

        __syncthreads();
        if (kt + 2 <= qt) load_kv(kt + 2, buf);
        cp_commit();
        buf ^= 1;
    }

    const float i0 = 1.f / l0, i1 = 1.f / l1;
    __half* Ob = O + ((size_t)(b*Sn + qt*64 + wid*16))*Dn + h*DHn;
    #pragma unroll
    for (int j = 0; j < 8; ++j) {
        *(uint32_t*)&Ob[(size_t)(g    )*Dn + j*8 + t*2] = pack2(o[j][0]*i0, o[j][1]*i0);
        *(uint32_t*)&Ob[(size_t)(g + 8)*Dn + j*8 + t*2] = pack2(o[j][2]*i1, o[j][3]*i1);
    }
}

// ==================== launch ====================
extern "C" void kernel_launch(void* const* d_in, const int* in_sizes, int n_in,
                              void* d_out, int out_size) {
    const float* x     = (const float*)d_in[0];
    const int*   amask = (const int*)  d_in[1];
    const float* Wq    = (const float*)d_in[2];
    const float* Wk    = (const float*)d_in[3];
    const float* Wv    = (const float*)d_in[4];
    const float* Wo    = (const float*)d_in[5];
    const float* W1    = (const float*)d_in[6];
    const float* W2    = (const float*)d_in[7];
    const float* gamma1= (const float*)d_in[8];
    const float* beta1 = (const float*)d_in[9];
    const float* gamma2= (const float*)d_in[10];
    const float* beta2 = (const float*)d_in[11];
    float* out = (float*)d_out;

    __half *xn1, *q, *k, *v, *attn, *xn2, *glu, *wh, *hbuf;
    float *x1;
    cudaGetSymbolAddress((void**)&xn1,  g_xn1);
    cudaGetSymbolAddress((void**)&q,    g_q);
    cudaGetSymbolAddress((void**)&k,    g_k);
    cudaGetSymbolAddress((void**)&v,    g_v);
    cudaGetSymbolAddress((void**)&attn, g_attn);
    cudaGetSymbolAddress((void**)&x1,   g_x1);
    cudaGetSymbolAddress((void**)&xn2,  g_xn2);
    cudaGetSymbolAddress((void**)&hbuf, g_h);
    cudaGetSymbolAddress((void**)&glu,  g_glu);
    cudaGetSymbolAddress((void**)&wh,   g_wh);

    cudaFuncSetAttribute(attn_f16, cudaFuncAttributeMaxDynamicSharedMemorySize, ATTN_SMEM);
    cudaFuncSetAttribute(gemm_qkv, cudaFuncAttributeMaxDynamicSharedMemorySize, GT_SMEM);
    cudaFuncSetAttribute((const void*)gemm_k<false,true>,  cudaFuncAttributeMaxDynamicSharedMemorySize, GT_SMEM);
    cudaFuncSetAttribute((const void*)gemm_k<true,false>,  cudaFuncAttributeMaxDynamicSharedMemorySize, GT_SMEM);

    // 0. fused weight convert+transpose (single launch)
    cvtw_all<<<10240, 256>>>(Wq, Wk, Wv, Wo, W1, W2, wh);

    // 1. LN1 -> fp16
    ln_kernel<<<Mn, 256>>>(x, gamma1, beta1, xn1);

    // 2. fused Q,K,V projections -> fp16 (q pre-scaled)
    dim3 gQKV(Dn/BN, Mn/BM, 3);
    gemm_qkv<<<gQKV, 256, GT_SMEM>>>(xn1, wh, q, k, v);

    // 3. causal attention -> fp16
    dim3 gA(Sn/64, Hn, Bn);
    attn_f16<<<gA, 128, ATTN_SMEM>>>(q, k, v, amask, attn);

    // 4. output projection + residual -> fp32 x1
    dim3 gD(Dn/BN, Mn/BM);
    gemm_k<true,false><<<gD, 256, GT_SMEM>>>(attn, wh + WOFF_O, x, x1, Mn, Dn, Dn);

    // 5. LN2 -> fp16
    ln_kernel<<<Mn, 256>>>(x1, gamma2, beta2, xn2);

    // 6. W1 (N=4096) -> fp16 h
    dim3 gF(DFF/BN, Mn/BM);
    gemm_k<false,true><<<gF, 256, GT_SMEM>>>(xn2, wh + WOFF_1, nullptr, hbuf, Mn, DFF, Dn);

    // 7. GLU -> fp16
    glu_kernel<<<(Mn*DG/4)/256, 256>>>(hbuf, glu);

    // 8. W2 + residual -> fp32 out
    gemm_k<true,false><<<gD, 256, GT_SMEM>>>(glu, wh + WOFF_2, x1, out, Mn, Dn, DG);
}